// round 1
// baseline (speedup 1.0000x reference)
#include <cuda_runtime.h>
#include <math.h>

#define Bb 4
#define T 1024
#define C 1024
#define NH 16
#define HD 64
#define E 8
#define TOPK 2
#define FF 4096
#define BT (Bb*T)       // 4096
#define BH (Bb*NH)      // 64
#define NASSIGN (BT*TOPK) // 8192

// ---------------- scratch (static device allocations) ----------------
__device__ float g_h  [BT*C];
__device__ float g_q  [BT*C];
__device__ float g_k  [BT*C];
__device__ float g_v  [BT*C];
__device__ float g_S  [(size_t)BH*T*T];   // 256 MB attention scores
__device__ float g_y  [BT*C];
__device__ float g_x1 [BT*C];
__device__ float g_h2 [BT*C];
__device__ float g_h1 [(size_t)NASSIGN*FF]; // 134 MB expert hidden
__device__ int   g_cnt[E];
__device__ int   g_off[E];
__device__ int   g_expidx[NASSIGN];
__device__ int   g_pos  [NASSIGN];
__device__ float g_gscore[NASSIGN];
__device__ int   g_list [NASSIGN];      // slot -> token
__device__ float g_slotscore[NASSIGN];  // slot -> gate score

__device__ __forceinline__ float4 ld4(const float* p){ return *reinterpret_cast<const float4*>(p); }

// ---------------- layernorm ----------------
__global__ void ln_kernel(const float* __restrict__ x, const float* __restrict__ g,
                          const float* __restrict__ b, float* __restrict__ out)
{
    int row = blockIdx.x;
    const float* xr = x + (size_t)row * C;
    int t = threadIdx.x;
    float v[4]; float s = 0.f, s2 = 0.f;
#pragma unroll
    for (int i = 0; i < 4; i++) { float val = xr[t + 256*i]; v[i] = val; s += val; s2 += val*val; }
#pragma unroll
    for (int o = 16; o; o >>= 1) { s += __shfl_xor_sync(0xffffffffu, s, o); s2 += __shfl_xor_sync(0xffffffffu, s2, o); }
    __shared__ float sh[8], sh2[8];
    int w = t >> 5, lane = t & 31;
    if (!lane) { sh[w] = s; sh2[w] = s2; }
    __syncthreads();
    __shared__ float mean_s, rstd_s;
    if (t == 0) {
        float S = 0.f, S2 = 0.f;
#pragma unroll
        for (int i = 0; i < 8; i++) { S += sh[i]; S2 += sh2[i]; }
        float mean = S * (1.f/C);
        float var  = S2 * (1.f/C) - mean*mean;
        mean_s = mean; rstd_s = rsqrtf(var + 1e-5f);
    }
    __syncthreads();
    float mean = mean_s, rstd = rstd_s;
    float* orow = out + (size_t)row * C;
#pragma unroll
    for (int i = 0; i < 4; i++) { int c = t + 256*i; orow[c] = (v[i] - mean) * rstd * g[c] + b[c]; }
}

// ---------------- generic SGEMM C = A * B^T  (A:[M,K] lda, B:[N,K] ldb) ----------------
__global__ __launch_bounds__(256) void gemm_nt(const float* __restrict__ A, int lda,
                                               const float* __restrict__ Bw, int ldb,
                                               float* __restrict__ Cc, int ldc,
                                               int M, int N, int K)
{
    __shared__ float As[8][128];
    __shared__ float Bs[8][128];
    int tid = threadIdx.x;
    int tx = tid & 15, ty = tid >> 4;
    int rowBase = blockIdx.y * 128;
    int colBase = blockIdx.x * 128;
    float acc[8][8];
#pragma unroll
    for (int i = 0; i < 8; i++)
#pragma unroll
        for (int j = 0; j < 8; j++) acc[i][j] = 0.f;
    int lr = tid >> 1;
    int lc = (tid & 1) << 2;
    for (int k0 = 0; k0 < K; k0 += 8) {
        float4 av = make_float4(0,0,0,0), bv = make_float4(0,0,0,0);
        int ar = rowBase + lr;
        if (ar < M) av = ld4(A + (size_t)ar*lda + k0 + lc);
        int br = colBase + lr;
        if (br < N) bv = ld4(Bw + (size_t)br*ldb + k0 + lc);
        As[lc+0][lr]=av.x; As[lc+1][lr]=av.y; As[lc+2][lr]=av.z; As[lc+3][lr]=av.w;
        Bs[lc+0][lr]=bv.x; Bs[lc+1][lr]=bv.y; Bs[lc+2][lr]=bv.z; Bs[lc+3][lr]=bv.w;
        __syncthreads();
#pragma unroll
        for (int kk = 0; kk < 8; kk++) {
            float4 a0 = ld4(&As[kk][ty*8]), a1 = ld4(&As[kk][ty*8+4]);
            float4 b0 = ld4(&Bs[kk][tx*8]), b1 = ld4(&Bs[kk][tx*8+4]);
            float ra[8] = {a0.x,a0.y,a0.z,a0.w,a1.x,a1.y,a1.z,a1.w};
            float rb[8] = {b0.x,b0.y,b0.z,b0.w,b1.x,b1.y,b1.z,b1.w};
#pragma unroll
            for (int i = 0; i < 8; i++)
#pragma unroll
                for (int j = 0; j < 8; j++) acc[i][j] = fmaf(ra[i], rb[j], acc[i][j]);
        }
        __syncthreads();
    }
#pragma unroll
    for (int i = 0; i < 8; i++) {
        int r = rowBase + ty*8 + i;
        if (r >= M) continue;
        float* crow = Cc + (size_t)r * ldc;
#pragma unroll
        for (int j = 0; j < 8; j++) {
            int c = colBase + tx*8 + j;
            if (c < N) crow[c] = acc[i][j];
        }
    }
}

// ---------------- Wo: out = res + A*B^T + bias, dual-write ----------------
__global__ __launch_bounds__(256) void gemm_wo(const float* __restrict__ A,
                                               const float* __restrict__ Bw,
                                               const float* __restrict__ bias,
                                               const float* __restrict__ res,
                                               float* __restrict__ C1,
                                               float* __restrict__ C2)
{
    __shared__ float As[8][128];
    __shared__ float Bs[8][128];
    int tid = threadIdx.x;
    int tx = tid & 15, ty = tid >> 4;
    int rowBase = blockIdx.y * 128;
    int colBase = blockIdx.x * 128;
    float acc[8][8];
#pragma unroll
    for (int i = 0; i < 8; i++)
#pragma unroll
        for (int j = 0; j < 8; j++) acc[i][j] = 0.f;
    int lr = tid >> 1;
    int lc = (tid & 1) << 2;
    for (int k0 = 0; k0 < C; k0 += 8) {
        float4 av = ld4(A + (size_t)(rowBase+lr)*C + k0 + lc);
        float4 bv = ld4(Bw + (size_t)(colBase+lr)*C + k0 + lc);
        As[lc+0][lr]=av.x; As[lc+1][lr]=av.y; As[lc+2][lr]=av.z; As[lc+3][lr]=av.w;
        Bs[lc+0][lr]=bv.x; Bs[lc+1][lr]=bv.y; Bs[lc+2][lr]=bv.z; Bs[lc+3][lr]=bv.w;
        __syncthreads();
#pragma unroll
        for (int kk = 0; kk < 8; kk++) {
            float4 a0 = ld4(&As[kk][ty*8]), a1 = ld4(&As[kk][ty*8+4]);
            float4 b0 = ld4(&Bs[kk][tx*8]), b1 = ld4(&Bs[kk][tx*8+4]);
            float ra[8] = {a0.x,a0.y,a0.z,a0.w,a1.x,a1.y,a1.z,a1.w};
            float rb[8] = {b0.x,b0.y,b0.z,b0.w,b1.x,b1.y,b1.z,b1.w};
#pragma unroll
            for (int i = 0; i < 8; i++)
#pragma unroll
                for (int j = 0; j < 8; j++) acc[i][j] = fmaf(ra[i], rb[j], acc[i][j]);
        }
        __syncthreads();
    }
#pragma unroll
    for (int i = 0; i < 8; i++) {
        int r = rowBase + ty*8 + i;
#pragma unroll
        for (int j = 0; j < 8; j++) {
            int c = colBase + tx*8 + j;
            float v = res[(size_t)r*C + c] + acc[i][j] + bias[c];
            C1[(size_t)r*C + c] = v;
            C2[(size_t)r*C + c] = v;
        }
    }
}

// ---------------- attention scores: S = q*k^T/8 with causal mask ----------------
__global__ __launch_bounds__(256) void gemm_scores()
{
    int z = blockIdx.z; int bb = z >> 4; int hh = z & 15;
    const float* A  = g_q + (size_t)bb*T*C + hh*HD;
    const float* Bw = g_k + (size_t)bb*T*C + hh*HD;
    float* Cc = g_S + (size_t)z*T*T;
    int rowBase = blockIdx.y * 128;  // query
    int colBase = blockIdx.x * 128;  // key
    int tid = threadIdx.x;
    int tx = tid & 15, ty = tid >> 4;
    if (colBase >= rowBase + 128) {  // fully masked tile
#pragma unroll
        for (int i = 0; i < 8; i++) {
            float* crow = Cc + (size_t)(rowBase + ty*8 + i) * T;
#pragma unroll
            for (int j = 0; j < 8; j++) crow[colBase + tx*8 + j] = -1e30f;
        }
        return;
    }
    __shared__ float As[8][128];
    __shared__ float Bs[8][128];
    float acc[8][8];
#pragma unroll
    for (int i = 0; i < 8; i++)
#pragma unroll
        for (int j = 0; j < 8; j++) acc[i][j] = 0.f;
    int lr = tid >> 1;
    int lc = (tid & 1) << 2;
    for (int k0 = 0; k0 < HD; k0 += 8) {
        float4 av = ld4(A  + (size_t)(rowBase+lr)*C + k0 + lc);
        float4 bv = ld4(Bw + (size_t)(colBase+lr)*C + k0 + lc);
        As[lc+0][lr]=av.x; As[lc+1][lr]=av.y; As[lc+2][lr]=av.z; As[lc+3][lr]=av.w;
        Bs[lc+0][lr]=bv.x; Bs[lc+1][lr]=bv.y; Bs[lc+2][lr]=bv.z; Bs[lc+3][lr]=bv.w;
        __syncthreads();
#pragma unroll
        for (int kk = 0; kk < 8; kk++) {
            float4 a0 = ld4(&As[kk][ty*8]), a1 = ld4(&As[kk][ty*8+4]);
            float4 b0 = ld4(&Bs[kk][tx*8]), b1 = ld4(&Bs[kk][tx*8+4]);
            float ra[8] = {a0.x,a0.y,a0.z,a0.w,a1.x,a1.y,a1.z,a1.w};
            float rb[8] = {b0.x,b0.y,b0.z,b0.w,b1.x,b1.y,b1.z,b1.w};
#pragma unroll
            for (int i = 0; i < 8; i++)
#pragma unroll
                for (int j = 0; j < 8; j++) acc[i][j] = fmaf(ra[i], rb[j], acc[i][j]);
        }
        __syncthreads();
    }
#pragma unroll
    for (int i = 0; i < 8; i++) {
        int r = rowBase + ty*8 + i;
        float* crow = Cc + (size_t)r * T;
#pragma unroll
        for (int j = 0; j < 8; j++) {
            int c = colBase + tx*8 + j;
            crow[c] = (c <= r) ? acc[i][j] * 0.125f : -1e30f;
        }
    }
}

// ---------------- row softmax over S ----------------
__global__ void softmax_kernel()
{
    size_t row = blockIdx.x;
    float* r = g_S + row * T;
    int t = threadIdx.x;
    float v[4]; float m = -1e30f;
#pragma unroll
    for (int i = 0; i < 4; i++) { v[i] = r[t + 256*i]; m = fmaxf(m, v[i]); }
#pragma unroll
    for (int o = 16; o; o >>= 1) m = fmaxf(m, __shfl_xor_sync(0xffffffffu, m, o));
    __shared__ float sh[8];
    int w = t >> 5, lane = t & 31;
    if (!lane) sh[w] = m;
    __syncthreads();
    __shared__ float m_s, inv_s;
    if (t == 0) {
        float mm = sh[0];
#pragma unroll
        for (int i = 1; i < 8; i++) mm = fmaxf(mm, sh[i]);
        m_s = mm;
    }
    __syncthreads();
    m = m_s;
    float s = 0.f;
#pragma unroll
    for (int i = 0; i < 4; i++) { v[i] = expf(v[i] - m); s += v[i]; }
#pragma unroll
    for (int o = 16; o; o >>= 1) s += __shfl_xor_sync(0xffffffffu, s, o);
    if (!lane) sh[w] = s;
    __syncthreads();
    if (t == 0) {
        float ss = 0.f;
#pragma unroll
        for (int i = 0; i < 8; i++) ss += sh[i];
        inv_s = 1.f / ss;
    }
    __syncthreads();
    float inv = inv_s;
#pragma unroll
    for (int i = 0; i < 4; i++) r[t + 256*i] = v[i] * inv;
}

// ---------------- AV: y = S * v  (GEMM NN, N=64) ----------------
__global__ __launch_bounds__(256) void gemm_av()
{
    int z = blockIdx.z; int bb = z >> 4; int hh = z & 15;
    const float* A  = g_S + (size_t)z*T*T;           // [T,T]
    const float* Bm = g_v + (size_t)bb*T*C + hh*HD;  // [T,64] stride C
    float* Cc = g_y + (size_t)bb*T*C + hh*HD;        // stride C
    int rowBase = blockIdx.y * 128;
    int colBase = blockIdx.x * 128;  // always 0
    int tid = threadIdx.x;
    int tx = tid & 15, ty = tid >> 4;
    __shared__ float As[8][128];
    __shared__ float Bs[8][128];
    float acc[8][8];
#pragma unroll
    for (int i = 0; i < 8; i++)
#pragma unroll
        for (int j = 0; j < 8; j++) acc[i][j] = 0.f;
    int lr = tid >> 1;
    int lc = (tid & 1) << 2;
    int brow = tid >> 5;
    int bcol = (tid & 31) << 2;
    for (int k0 = 0; k0 < T; k0 += 8) {
        float4 av = ld4(A + (size_t)(rowBase+lr)*T + k0 + lc);
        As[lc+0][lr]=av.x; As[lc+1][lr]=av.y; As[lc+2][lr]=av.z; As[lc+3][lr]=av.w;
        float4 bv = make_float4(0,0,0,0);
        if (colBase + bcol < HD) bv = ld4(Bm + (size_t)(k0+brow)*C + colBase + bcol);
        Bs[brow][bcol+0]=bv.x; Bs[brow][bcol+1]=bv.y; Bs[brow][bcol+2]=bv.z; Bs[brow][bcol+3]=bv.w;
        __syncthreads();
#pragma unroll
        for (int kk = 0; kk < 8; kk++) {
            float4 a0 = ld4(&As[kk][ty*8]), a1 = ld4(&As[kk][ty*8+4]);
            float4 b0 = ld4(&Bs[kk][tx*8]), b1 = ld4(&Bs[kk][tx*8+4]);
            float ra[8] = {a0.x,a0.y,a0.z,a0.w,a1.x,a1.y,a1.z,a1.w};
            float rb[8] = {b0.x,b0.y,b0.z,b0.w,b1.x,b1.y,b1.z,b1.w};
#pragma unroll
            for (int i = 0; i < 8; i++)
#pragma unroll
                for (int j = 0; j < 8; j++) acc[i][j] = fmaf(ra[i], rb[j], acc[i][j]);
        }
        __syncthreads();
    }
#pragma unroll
    for (int i = 0; i < 8; i++) {
        int r = rowBase + ty*8 + i;
        float* crow = Cc + (size_t)r * C;
#pragma unroll
        for (int j = 0; j < 8; j++) {
            int c = colBase + tx*8 + j;
            if (c < HD) crow[c] = acc[i][j];
        }
    }
}

// ---------------- gate: logits, softmax over 8, top-2, counts ----------------
__global__ void gate_kernel(const float* __restrict__ gW, const float* __restrict__ gb)
{
    int token = blockIdx.x * 4 + (threadIdx.x >> 5);
    int lane = threadIdx.x & 31;
    const float* hr = g_h2 + (size_t)token * C;
    float logits[E];
#pragma unroll
    for (int e = 0; e < E; e++) {
        const float* wr = gW + (size_t)e * C;
        float s = 0.f;
        for (int j = lane; j < C; j += 32) s += hr[j] * wr[j];
#pragma unroll
        for (int o = 16; o; o >>= 1) s += __shfl_xor_sync(0xffffffffu, s, o);
        logits[e] = s + gb[e];
    }
    if (lane == 0) {
        int i0 = 0; float m0 = logits[0];
#pragma unroll
        for (int e = 1; e < E; e++) if (logits[e] > m0) { m0 = logits[e]; i0 = e; }
        int i1 = -1; float m1 = -1e30f;
#pragma unroll
        for (int e = 0; e < E; e++) if (e != i0 && logits[e] > m1) { m1 = logits[e]; i1 = e; }
        float den = 0.f;
#pragma unroll
        for (int e = 0; e < E; e++) den += expf(logits[e] - m0);
        float s0 = 1.f / den;
        float s1 = expf(m1 - m0) / den;
        g_expidx[token*2+0] = i0; g_gscore[token*2+0] = s0;
        g_expidx[token*2+1] = i1; g_gscore[token*2+1] = s1;
        g_pos[token*2+0] = atomicAdd(&g_cnt[i0], 1);
        g_pos[token*2+1] = atomicAdd(&g_cnt[i1], 1);
    }
}

__global__ void zero_cnt_kernel() { if (threadIdx.x < E) g_cnt[threadIdx.x] = 0; }

__global__ void scan_kernel()
{
    if (threadIdx.x == 0) {
        int acc = 0;
        for (int e = 0; e < E; e++) { g_off[e] = acc; acc += g_cnt[e]; }
    }
}

__global__ void scatter_kernel()
{
    int i = blockIdx.x * 256 + threadIdx.x;
    if (i < NASSIGN) {
        int e = g_expidx[i];
        int slot = g_off[e] + g_pos[i];
        g_list[slot] = i >> 1;
        g_slotscore[slot] = g_gscore[i];
    }
}

// ---------------- fc: h1[slot] = gelu(h2[token] * fc_W[e]^T + fc_b[e]) ----------------
__global__ __launch_bounds__(256) void gemm_fc(const float* __restrict__ fcW,
                                               const float* __restrict__ fcb)
{
    int e = blockIdx.z;
    int cnt = g_cnt[e], off = g_off[e];
    int rowBase = blockIdx.y * 128;
    if (rowBase >= cnt) return;
    int colBase = blockIdx.x * 128;
    const float* Bw = fcW + (size_t)e * FF * C;
    int tid = threadIdx.x;
    int tx = tid & 15, ty = tid >> 4;
    __shared__ float As[8][128];
    __shared__ float Bs[8][128];
    __shared__ int rowTok[128];
    if (tid < 128) {
        int r = rowBase + tid;
        rowTok[tid] = (r < cnt) ? g_list[off + r] : -1;
    }
    __syncthreads();
    float acc[8][8];
#pragma unroll
    for (int i = 0; i < 8; i++)
#pragma unroll
        for (int j = 0; j < 8; j++) acc[i][j] = 0.f;
    int lr = tid >> 1;
    int lc = (tid & 1) << 2;
    int tokA = rowTok[lr];
    for (int k0 = 0; k0 < C; k0 += 8) {
        float4 av = make_float4(0,0,0,0);
        if (tokA >= 0) av = ld4(g_h2 + (size_t)tokA*C + k0 + lc);
        float4 bv = ld4(Bw + (size_t)(colBase+lr)*C + k0 + lc);
        As[lc+0][lr]=av.x; As[lc+1][lr]=av.y; As[lc+2][lr]=av.z; As[lc+3][lr]=av.w;
        Bs[lc+0][lr]=bv.x; Bs[lc+1][lr]=bv.y; Bs[lc+2][lr]=bv.z; Bs[lc+3][lr]=bv.w;
        __syncthreads();
#pragma unroll
        for (int kk = 0; kk < 8; kk++) {
            float4 a0 = ld4(&As[kk][ty*8]), a1 = ld4(&As[kk][ty*8+4]);
            float4 b0 = ld4(&Bs[kk][tx*8]), b1 = ld4(&Bs[kk][tx*8+4]);
            float ra[8] = {a0.x,a0.y,a0.z,a0.w,a1.x,a1.y,a1.z,a1.w};
            float rb[8] = {b0.x,b0.y,b0.z,b0.w,b1.x,b1.y,b1.z,b1.w};
#pragma unroll
            for (int i = 0; i < 8; i++)
#pragma unroll
                for (int j = 0; j < 8; j++) acc[i][j] = fmaf(ra[i], rb[j], acc[i][j]);
        }
        __syncthreads();
    }
    const float* fb = fcb + (size_t)e * FF;
#pragma unroll
    for (int i = 0; i < 8; i++) {
        int r = rowBase + ty*8 + i;
        if (r >= cnt) continue;
        float* crow = g_h1 + (size_t)(off + r) * FF;
#pragma unroll
        for (int j = 0; j < 8; j++) {
            int c = colBase + tx*8 + j;
            float v = acc[i][j] + fb[c];
            crow[c] = v * 0.5f * (1.f + erff(v * 0.70710678118654752f));
        }
    }
}

// ---------------- pj: out[token] += score * (h1[slot] * pj_W[e]^T + pj_b[e]) ----------------
__global__ __launch_bounds__(256) void gemm_pj(const float* __restrict__ pjW,
                                               const float* __restrict__ pjb,
                                               float* __restrict__ outp)
{
    int e = blockIdx.z;
    int cnt = g_cnt[e], off = g_off[e];
    int rowBase = blockIdx.y * 128;
    if (rowBase >= cnt) return;
    int colBase = blockIdx.x * 128;
    const float* A  = g_h1 + (size_t)off * FF;
    const float* Bw = pjW + (size_t)e * C * FF;
    int tid = threadIdx.x;
    int tx = tid & 15, ty = tid >> 4;
    __shared__ float As[8][128];
    __shared__ float Bs[8][128];
    float acc[8][8];
#pragma unroll
    for (int i = 0; i < 8; i++)
#pragma unroll
        for (int j = 0; j < 8; j++) acc[i][j] = 0.f;
    int lr = tid >> 1;
    int lc = (tid & 1) << 2;
    for (int k0 = 0; k0 < FF; k0 += 8) {
        float4 av = make_float4(0,0,0,0);
        int ar = rowBase + lr;
        if (ar < cnt) av = ld4(A + (size_t)ar*FF + k0 + lc);
        float4 bv = ld4(Bw + (size_t)(colBase+lr)*FF + k0 + lc);
        As[lc+0][lr]=av.x; As[lc+1][lr]=av.y; As[lc+2][lr]=av.z; As[lc+3][lr]=av.w;
        Bs[lc+0][lr]=bv.x; Bs[lc+1][lr]=bv.y; Bs[lc+2][lr]=bv.z; Bs[lc+3][lr]=bv.w;
        __syncthreads();
#pragma unroll
        for (int kk = 0; kk < 8; kk++) {
            float4 a0 = ld4(&As[kk][ty*8]), a1 = ld4(&As[kk][ty*8+4]);
            float4 b0 = ld4(&Bs[kk][tx*8]), b1 = ld4(&Bs[kk][tx*8+4]);
            float ra[8] = {a0.x,a0.y,a0.z,a0.w,a1.x,a1.y,a1.z,a1.w};
            float rb[8] = {b0.x,b0.y,b0.z,b0.w,b1.x,b1.y,b1.z,b1.w};
#pragma unroll
            for (int i = 0; i < 8; i++)
#pragma unroll
                for (int j = 0; j < 8; j++) acc[i][j] = fmaf(ra[i], rb[j], acc[i][j]);
        }
        __syncthreads();
    }
    const float* pb = pjb + (size_t)e * C;
#pragma unroll
    for (int i = 0; i < 8; i++) {
        int r = rowBase + ty*8 + i;
        if (r >= cnt) continue;
        int tok = g_list[off + r];
        float sc = g_slotscore[off + r];
        float* orow = outp + (size_t)tok * C;
#pragma unroll
        for (int j = 0; j < 8; j++) {
            int c = colBase + tx*8 + j;
            atomicAdd(&orow[c], sc * (acc[i][j] + pb[c]));
        }
    }
}

// ---------------- host launcher ----------------
extern "C" void kernel_launch(void* const* d_in, const int* in_sizes, int n_in,
                              void* d_out, int out_size)
{
    const float* x     = (const float*)d_in[0];
    const float* ln1g  = (const float*)d_in[1];
    const float* ln1b  = (const float*)d_in[2];
    const float* Wq    = (const float*)d_in[3];
    const float* Wk    = (const float*)d_in[4];
    const float* Wv    = (const float*)d_in[5];
    const float* Wo    = (const float*)d_in[6];
    const float* bo    = (const float*)d_in[7];
    const float* ln2g  = (const float*)d_in[8];
    const float* ln2b  = (const float*)d_in[9];
    const float* gateW = (const float*)d_in[10];
    const float* gateb = (const float*)d_in[11];
    const float* fcW   = (const float*)d_in[12];
    const float* fcb   = (const float*)d_in[13];
    const float* pjW   = (const float*)d_in[14];
    const float* pjb   = (const float*)d_in[15];
    float* outp = (float*)d_out;

    float *p_h, *p_q, *p_k, *p_v, *p_y, *p_x1, *p_h2;
    cudaGetSymbolAddress((void**)&p_h,  g_h);
    cudaGetSymbolAddress((void**)&p_q,  g_q);
    cudaGetSymbolAddress((void**)&p_k,  g_k);
    cudaGetSymbolAddress((void**)&p_v,  g_v);
    cudaGetSymbolAddress((void**)&p_y,  g_y);
    cudaGetSymbolAddress((void**)&p_x1, g_x1);
    cudaGetSymbolAddress((void**)&p_h2, g_h2);

    zero_cnt_kernel<<<1, 32>>>();

    // LN1
    ln_kernel<<<BT, 256>>>(x, ln1g, ln1b, p_h);

    // QKV projections
    dim3 gQKV(C/128, BT/128);
    gemm_nt<<<gQKV, 256>>>(p_h, C, Wq, C, p_q, C, BT, C, C);
    gemm_nt<<<gQKV, 256>>>(p_h, C, Wk, C, p_k, C, BT, C, C);
    gemm_nt<<<gQKV, 256>>>(p_h, C, Wv, C, p_v, C, BT, C, C);

    // attention
    gemm_scores<<<dim3(T/128, T/128, BH), 256>>>();
    softmax_kernel<<<BH*T, 256>>>();
    gemm_av<<<dim3(1, T/128, BH), 256>>>();

    // output projection + residual (writes g_x1 and d_out)
    gemm_wo<<<dim3(C/128, BT/128), 256>>>(p_y, Wo, bo, x, p_x1, outp);

    // LN2
    ln_kernel<<<BT, 256>>>(p_x1, ln2g, ln2b, p_h2);

    // gating + routing
    gate_kernel<<<BT/4, 128>>>(gateW, gateb);
    scan_kernel<<<1, 32>>>();
    scatter_kernel<<<NASSIGN/256, 256>>>();

    // expert FFN (routed, top-2 only)
    gemm_fc<<<dim3(FF/128, BT/128, E), 256>>>(fcW, fcb);
    gemm_pj<<<dim3(C/128, BT/128, E), 256>>>(pjW, pjb, outp);
}

// round 6
// speedup vs baseline: 2.0835x; 2.0835x over previous
#include <cuda_runtime.h>
#include <math.h>
#include <stdint.h>

#define Bb 4
#define T 1024
#define C 1024
#define NH 16
#define HD 64
#define E 8
#define TOPK 2
#define FF 4096
#define BT (Bb*T)
#define BH (Bb*NH)
#define NASSIGN (BT*TOPK)

// MMA smem tile: 128 rows x 32 floats, padded stride 36 floats (144B)
#define TILEB (128*144)      // 18432 bytes
#define DYNSMEM (4*TILEB)    // A0,A1,B0,B1 = 73728

// ---------------- scratch ----------------
__device__ float g_h  [BT*C];
__device__ float g_q  [BT*C];
__device__ float g_k  [BT*C];
__device__ float g_v  [BT*C];
__device__ float g_S  [(size_t)BH*T*T];
__device__ float g_y  [BT*C];
__device__ float g_x1 [BT*C];
__device__ float g_h2 [BT*C];    // exact (gate)
__device__ float g_h2r[BT*C];    // tf32-rounded (fc A)
__device__ float g_h1 [(size_t)NASSIGN*FF];
__device__ float g_fcw[(size_t)E*FF*C];
__device__ float g_pjw[(size_t)E*C*FF];
__device__ int   g_cnt[E];
__device__ int   g_off[E];
__device__ int   g_expidx[NASSIGN];
__device__ int   g_pos  [NASSIGN];
__device__ float g_gscore[NASSIGN];
__device__ int   g_list [NASSIGN];
__device__ float g_slotscore[NASSIGN];

__device__ __forceinline__ float4 ld4(const float* p){ return *reinterpret_cast<const float4*>(p); }
__device__ __forceinline__ float tf32r(float x){
    float o; asm("cvt.rna.tf32.f32 %0, %1;" : "=f"(o) : "f"(x)); return o;
}

// ---------------- PTX helpers ----------------
__device__ __forceinline__ uint32_t smem_u32(const void* p){
    uint32_t a; asm("{ .reg .u64 t; cvta.to.shared.u64 t, %1; cvt.u32.u64 %0, t; }" : "=r"(a) : "l"(p)); return a;
}
__device__ __forceinline__ void cpa16(uint32_t saddr, const void* g, uint32_t srcsize){
    asm volatile("cp.async.cg.shared.global [%0], [%1], 16, %2;" :: "r"(saddr), "l"(g), "r"(srcsize) : "memory");
}
#define CPA_COMMIT() asm volatile("cp.async.commit_group;" ::: "memory")
#define CPA_WAIT1()  asm volatile("cp.async.wait_group 1;" ::: "memory")
#define CPA_WAIT0()  asm volatile("cp.async.wait_group 0;" ::: "memory")

__device__ __forceinline__ void ldsm_x4(uint32_t &r0, uint32_t &r1, uint32_t &r2, uint32_t &r3, uint32_t addr){
    asm volatile("ldmatrix.sync.aligned.m8n8.x4.shared.b16 {%0,%1,%2,%3},[%4];"
                 : "=r"(r0),"=r"(r1),"=r"(r2),"=r"(r3) : "r"(addr));
}
__device__ __forceinline__ void mma_tf32(float* c, const uint32_t* a, const uint32_t* b){
    asm volatile("mma.sync.aligned.m16n8k8.row.col.f32.tf32.tf32.f32 "
                 "{%0,%1,%2,%3},{%4,%5,%6,%7},{%8,%9},{%0,%1,%2,%3};"
                 : "+f"(c[0]),"+f"(c[1]),"+f"(c[2]),"+f"(c[3])
                 : "r"(a[0]),"r"(a[1]),"r"(a[2]),"r"(a[3]), "r"(b[0]),"r"(b[1]));
}

// ---------------- tf32 MMA mainloop: Ctile[128,128] += A[128,K] * B[128,K]^T ----------------
__device__ __forceinline__ void gemm_mainloop(
    const float* const* rowA, const float* const* rowB,
    const float* dummy, int nchunk, char* sm,
    float acc[4][4][4], int tid)
{
    uint32_t base = smem_u32(sm);
    int lane = tid & 31, wid = tid >> 5;
    int warpM = wid >> 2, warpN = wid & 3;

    uint32_t a_off[4];
#pragma unroll
    for (int mi = 0; mi < 4; mi++) {
        int row = warpM*64 + mi*16 + (lane & 7) + ((lane >> 3) & 1)*8;
        int col4 = (lane >> 4) * 4;
        a_off[mi] = (uint32_t)row*144 + (uint32_t)col4*4;
    }
    uint32_t b_off[2];
#pragma unroll
    for (int p = 0; p < 2; p++) {
        int n = warpN*32 + p*16 + (lane & 7) + ((lane >> 4) * 8);
        int col4 = ((lane >> 3) & 1) * 4;
        b_off[p] = (uint32_t)n*144 + (uint32_t)col4*4;
    }

#define ISSUE(kc) do { \
        int b_ = (kc) & 1; \
        uint32_t sa_ = base + b_*TILEB; \
        uint32_t sb_ = base + 2*TILEB + b_*TILEB; \
        _Pragma("unroll") \
        for (int q = 0; q < 4; q++) { \
            int idx = tid + 256*q; \
            int row = idx >> 3, c16 = idx & 7; \
            uint32_t off = (uint32_t)row*144 + c16*16; \
            const float* pa = rowA[row]; \
            const void* ga = pa ? (const void*)(pa + (kc)*32 + c16*4) : (const void*)dummy; \
            cpa16(sa_ + off, ga, pa ? 16u : 0u); \
            cpa16(sb_ + off, rowB[row] + (kc)*32 + c16*4, 16u); \
        } \
        CPA_COMMIT(); \
    } while (0)

    ISSUE(0);
    for (int kc = 0; kc < nchunk; kc++) {
        if (kc + 1 < nchunk) { ISSUE(kc+1); CPA_WAIT1(); } else { CPA_WAIT0(); }
        __syncthreads();
        int b = kc & 1;
        uint32_t sa = base + b*TILEB;
        uint32_t sb = base + 2*TILEB + b*TILEB;
#pragma unroll
        for (int ks = 0; ks < 4; ks++) {
            uint32_t afr[4][4];
#pragma unroll
            for (int mi = 0; mi < 4; mi++)
                ldsm_x4(afr[mi][0], afr[mi][1], afr[mi][2], afr[mi][3], sa + a_off[mi] + ks*32);
            uint32_t bfr[4][2];
#pragma unroll
            for (int p = 0; p < 2; p++)
                ldsm_x4(bfr[2*p][0], bfr[2*p][1], bfr[2*p+1][0], bfr[2*p+1][1], sb + b_off[p] + ks*32);
#pragma unroll
            for (int mi = 0; mi < 4; mi++)
#pragma unroll
                for (int ni = 0; ni < 4; ni++)
                    mma_tf32(acc[mi][ni], afr[mi], bfr[ni]);
        }
        __syncthreads();
    }
#undef ISSUE
}

// ---------------- fc: gathered A, +bias, GELU, tf32-rounded out (tf32 MMA) ----------------
__global__ __launch_bounds__(256) void gemm_fc_tc(const float* __restrict__ fcb)
{
    int e = blockIdx.z;
    int cnt = g_cnt[e], off = g_off[e];
    int rowBase = blockIdx.y * 128;
    if (rowBase >= cnt) return;
    int colBase = blockIdx.x * 128;
    extern __shared__ char sm[];
    __shared__ const float* rowA[128];
    __shared__ const float* rowB[128];
    int tid = threadIdx.x;
    const float* wbase = g_fcw + (size_t)e * FF * C;
    if (tid < 128) {
        int r = rowBase + tid;
        rowA[tid] = (r < cnt) ? g_h2r + (size_t)g_list[off + r] * C : nullptr;
        rowB[tid] = wbase + (size_t)(colBase + tid) * C;
    }
    __syncthreads();
    float acc[4][4][4] = {};
    gemm_mainloop(rowA, rowB, wbase, C/32, sm, acc, tid);
    int lane = tid & 31, wid = tid >> 5, warpM = wid >> 2, warpN = wid & 3;
    int g = lane >> 2, tg = lane & 3;
    const float* fb = fcb + (size_t)e * FF;
#pragma unroll
    for (int mi = 0; mi < 4; mi++)
#pragma unroll
        for (int ni = 0; ni < 4; ni++) {
            int r0 = rowBase + warpM*64 + mi*16 + g;
            int cc = colBase + warpN*32 + ni*8 + tg*2;
#pragma unroll
            for (int h = 0; h < 2; h++) {
                int r = r0 + h*8;
                if (r >= cnt) continue;
                float v0 = acc[mi][ni][2*h+0] + fb[cc];
                float v1 = acc[mi][ni][2*h+1] + fb[cc+1];
                v0 = v0 * 0.5f * (1.f + erff(v0 * 0.70710678118654752f));
                v1 = v1 * 0.5f * (1.f + erff(v1 * 0.70710678118654752f));
                *(float2*)(g_h1 + (size_t)(off + r)*FF + cc) = make_float2(tf32r(v0), tf32r(v1));
            }
        }
}

// ---------------- pj: +bias, gate-scale, atomicAdd (tf32 MMA) ----------------
__global__ __launch_bounds__(256) void gemm_pj_tc(const float* __restrict__ pjb,
                                                  float* __restrict__ outp)
{
    int e = blockIdx.z;
    int cnt = g_cnt[e], off = g_off[e];
    int rowBase = blockIdx.y * 128;
    if (rowBase >= cnt) return;
    int colBase = blockIdx.x * 128;
    extern __shared__ char sm[];
    __shared__ const float* rowA[128];
    __shared__ const float* rowB[128];
    int tid = threadIdx.x;
    const float* wbase = g_pjw + (size_t)e * C * FF;
    if (tid < 128) {
        int r = rowBase + tid;
        rowA[tid] = (r < cnt) ? g_h1 + (size_t)(off + r) * FF : nullptr;
        rowB[tid] = wbase + (size_t)(colBase + tid) * FF;
    }
    __syncthreads();
    float acc[4][4][4] = {};
    gemm_mainloop(rowA, rowB, wbase, FF/32, sm, acc, tid);
    int lane = tid & 31, wid = tid >> 5, warpM = wid >> 2, warpN = wid & 3;
    int g = lane >> 2, tg = lane & 3;
    const float* pb = pjb + (size_t)e * C;
#pragma unroll
    for (int mi = 0; mi < 4; mi++)
#pragma unroll
        for (int ni = 0; ni < 4; ni++) {
            int r0 = rowBase + warpM*64 + mi*16 + g;
            int cc = colBase + warpN*32 + ni*8 + tg*2;
#pragma unroll
            for (int h = 0; h < 2; h++) {
                int r = r0 + h*8;
                if (r >= cnt) continue;
                int tok = g_list[off + r];
                float sc = g_slotscore[off + r];
                float* orow = outp + (size_t)tok * C;
                atomicAdd(&orow[cc],   sc * (acc[mi][ni][2*h+0] + pb[cc]));
                atomicAdd(&orow[cc+1], sc * (acc[mi][ni][2*h+1] + pb[cc+1]));
            }
        }
}

// ---------------- fp32 -> tf32-rounded fp32 ----------------
__global__ void conv_tf32(const float* __restrict__ in, float* __restrict__ out, int n4)
{
    int stride = gridDim.x * blockDim.x;
    for (int idx = blockIdx.x * blockDim.x + threadIdx.x; idx < n4; idx += stride) {
        float4 v = ((const float4*)in)[idx];
        v.x = tf32r(v.x); v.y = tf32r(v.y); v.z = tf32r(v.z); v.w = tf32r(v.w);
        ((float4*)out)[idx] = v;
    }
}

// ---------------- layernorm: exact fp32 out + optional tf32-rounded out ----------------
__global__ void ln_kernel(const float* __restrict__ x, const float* __restrict__ g,
                          const float* __restrict__ b, float* __restrict__ outf,
                          float* __restrict__ outr)
{
    int row = blockIdx.x;
    const float* xr = x + (size_t)row * C;
    int t = threadIdx.x;
    float v[4]; float s = 0.f, s2 = 0.f;
#pragma unroll
    for (int i = 0; i < 4; i++) { float val = xr[t + 256*i]; v[i] = val; s += val; s2 += val*val; }
#pragma unroll
    for (int o = 16; o; o >>= 1) { s += __shfl_xor_sync(0xffffffffu, s, o); s2 += __shfl_xor_sync(0xffffffffu, s2, o); }
    __shared__ float sh[8], sh2[8];
    int w = t >> 5, lane = t & 31;
    if (!lane) { sh[w] = s; sh2[w] = s2; }
    __syncthreads();
    __shared__ float mean_s, rstd_s;
    if (t == 0) {
        float S = 0.f, S2 = 0.f;
#pragma unroll
        for (int i = 0; i < 8; i++) { S += sh[i]; S2 += sh2[i]; }
        float mean = S * (1.f/C);
        float var  = S2 * (1.f/C) - mean*mean;
        mean_s = mean; rstd_s = rsqrtf(var + 1e-5f);
    }
    __syncthreads();
    float mean = mean_s, rstd = rstd_s;
#pragma unroll
    for (int i = 0; i < 4; i++) {
        int c = t + 256*i;
        float o = (v[i] - mean) * rstd * g[c] + b[c];
        outf[(size_t)row*C + c] = o;
        if (outr) outr[(size_t)row*C + c] = tf32r(o);
    }
}

// ---------------- generic SGEMM C = A * B^T (fp32 SIMT, round-1) ----------------
__global__ __launch_bounds__(256) void gemm_nt(const float* __restrict__ A, int lda,
                                               const float* __restrict__ Bw, int ldb,
                                               float* __restrict__ Cc, int ldc, int K)
{
    __shared__ float As[8][128];
    __shared__ float Bs[8][128];
    int tid = threadIdx.x;
    int tx = tid & 15, ty = tid >> 4;
    int rowBase = blockIdx.y * 128;
    int colBase = blockIdx.x * 128;
    float acc[8][8];
#pragma unroll
    for (int i = 0; i < 8; i++)
#pragma unroll
        for (int j = 0; j < 8; j++) acc[i][j] = 0.f;
    int lr = tid >> 1;
    int lc = (tid & 1) << 2;
    for (int k0 = 0; k0 < K; k0 += 8) {
        float4 av = ld4(A + (size_t)(rowBase+lr)*lda + k0 + lc);
        float4 bv = ld4(Bw + (size_t)(colBase+lr)*ldb + k0 + lc);
        As[lc+0][lr]=av.x; As[lc+1][lr]=av.y; As[lc+2][lr]=av.z; As[lc+3][lr]=av.w;
        Bs[lc+0][lr]=bv.x; Bs[lc+1][lr]=bv.y; Bs[lc+2][lr]=bv.z; Bs[lc+3][lr]=bv.w;
        __syncthreads();
#pragma unroll
        for (int kk = 0; kk < 8; kk++) {
            float4 a0 = ld4(&As[kk][ty*8]), a1 = ld4(&As[kk][ty*8+4]);
            float4 b0 = ld4(&Bs[kk][tx*8]), b1 = ld4(&Bs[kk][tx*8+4]);
            float ra[8] = {a0.x,a0.y,a0.z,a0.w,a1.x,a1.y,a1.z,a1.w};
            float rb[8] = {b0.x,b0.y,b0.z,b0.w,b1.x,b1.y,b1.z,b1.w};
#pragma unroll
            for (int i = 0; i < 8; i++)
#pragma unroll
                for (int j = 0; j < 8; j++) acc[i][j] = fmaf(ra[i], rb[j], acc[i][j]);
        }
        __syncthreads();
    }
#pragma unroll
    for (int i = 0; i < 8; i++) {
        int r = rowBase + ty*8 + i;
        float* crow = Cc + (size_t)r * ldc;
#pragma unroll
        for (int j = 0; j < 8; j++) crow[colBase + tx*8 + j] = acc[i][j];
    }
}

// ---------------- Wo: out = res + A*B^T + bias, dual-write (fp32 SIMT) ----------------
__global__ __launch_bounds__(256) void gemm_wo(const float* __restrict__ A,
                                               const float* __restrict__ Bw,
                                               const float* __restrict__ bias,
                                               const float* __restrict__ res,
                                               float* __restrict__ C1,
                                               float* __restrict__ C2)
{
    __shared__ float As[8][128];
    __shared__ float Bs[8][128];
    int tid = threadIdx.x;
    int tx = tid & 15, ty = tid >> 4;
    int rowBase = blockIdx.y * 128;
    int colBase = blockIdx.x * 128;
    float acc[8][8];
#pragma unroll
    for (int i = 0; i < 8; i++)
#pragma unroll
        for (int j = 0; j < 8; j++) acc[i][j] = 0.f;
    int lr = tid >> 1;
    int lc = (tid & 1) << 2;
    for (int k0 = 0; k0 < C; k0 += 8) {
        float4 av = ld4(A + (size_t)(rowBase+lr)*C + k0 + lc);
        float4 bv = ld4(Bw + (size_t)(colBase+lr)*C + k0 + lc);
        As[lc+0][lr]=av.x; As[lc+1][lr]=av.y; As[lc+2][lr]=av.z; As[lc+3][lr]=av.w;
        Bs[lc+0][lr]=bv.x; Bs[lc+1][lr]=bv.y; Bs[lc+2][lr]=bv.z; Bs[lc+3][lr]=bv.w;
        __syncthreads();
#pragma unroll
        for (int kk = 0; kk < 8; kk++) {
            float4 a0 = ld4(&As[kk][ty*8]), a1 = ld4(&As[kk][ty*8+4]);
            float4 b0 = ld4(&Bs[kk][tx*8]), b1 = ld4(&Bs[kk][tx*8+4]);
            float ra[8] = {a0.x,a0.y,a0.z,a0.w,a1.x,a1.y,a1.z,a1.w};
            float rb[8] = {b0.x,b0.y,b0.z,b0.w,b1.x,b1.y,b1.z,b1.w};
#pragma unroll
            for (int i = 0; i < 8; i++)
#pragma unroll
                for (int j = 0; j < 8; j++) acc[i][j] = fmaf(ra[i], rb[j], acc[i][j]);
        }
        __syncthreads();
    }
#pragma unroll
    for (int i = 0; i < 8; i++) {
        int r = rowBase + ty*8 + i;
#pragma unroll
        for (int j = 0; j < 8; j++) {
            int c = colBase + tx*8 + j;
            float v = res[(size_t)r*C + c] + acc[i][j] + bias[c];
            C1[(size_t)r*C + c] = v;
            C2[(size_t)r*C + c] = v;
        }
    }
}

// ---------------- attention scores (fp32, causal) ----------------
__global__ __launch_bounds__(256) void gemm_scores()
{
    int z = blockIdx.z; int bb = z >> 4; int hh = z & 15;
    const float* A  = g_q + (size_t)bb*T*C + hh*HD;
    const float* Bw = g_k + (size_t)bb*T*C + hh*HD;
    float* Cc = g_S + (size_t)z*T*T;
    int rowBase = blockIdx.y * 128;
    int colBase = blockIdx.x * 128;
    int tid = threadIdx.x;
    int tx = tid & 15, ty = tid >> 4;
    if (colBase >= rowBase + 128) {
#pragma unroll
        for (int i = 0; i < 8; i++) {
            float* crow = Cc + (size_t)(rowBase + ty*8 + i) * T;
#pragma unroll
            for (int j = 0; j < 8; j++) crow[colBase + tx*8 + j] = -1e30f;
        }
        return;
    }
    __shared__ float As[8][128];
    __shared__ float Bs[8][128];
    float acc[8][8];
#pragma unroll
    for (int i = 0; i < 8; i++)
#pragma unroll
        for (int j = 0; j < 8; j++) acc[i][j] = 0.f;
    int lr = tid >> 1;
    int lc = (tid & 1) << 2;
    for (int k0 = 0; k0 < HD; k0 += 8) {
        float4 av = ld4(A  + (size_t)(rowBase+lr)*C + k0 + lc);
        float4 bv = ld4(Bw + (size_t)(colBase+lr)*C + k0 + lc);
        As[lc+0][lr]=av.x; As[lc+1][lr]=av.y; As[lc+2][lr]=av.z; As[lc+3][lr]=av.w;
        Bs[lc+0][lr]=bv.x; Bs[lc+1][lr]=bv.y; Bs[lc+2][lr]=bv.z; Bs[lc+3][lr]=bv.w;
        __syncthreads();
#pragma unroll
        for (int kk = 0; kk < 8; kk++) {
            float4 a0 = ld4(&As[kk][ty*8]), a1 = ld4(&As[kk][ty*8+4]);
            float4 b0 = ld4(&Bs[kk][tx*8]), b1 = ld4(&Bs[kk][tx*8+4]);
            float ra[8] = {a0.x,a0.y,a0.z,a0.w,a1.x,a1.y,a1.z,a1.w};
            float rb[8] = {b0.x,b0.y,b0.z,b0.w,b1.x,b1.y,b1.z,b1.w};
#pragma unroll
            for (int i = 0; i < 8; i++)
#pragma unroll
                for (int j = 0; j < 8; j++) acc[i][j] = fmaf(ra[i], rb[j], acc[i][j]);
        }
        __syncthreads();
    }
#pragma unroll
    for (int i = 0; i < 8; i++) {
        int r = rowBase + ty*8 + i;
        float* crow = Cc + (size_t)r * T;
#pragma unroll
        for (int j = 0; j < 8; j++) {
            int c = colBase + tx*8 + j;
            crow[c] = (c <= r) ? acc[i][j] * 0.125f : -1e30f;
        }
    }
}

// ---------------- row softmax ----------------
__global__ void softmax_kernel()
{
    size_t row = blockIdx.x;
    float* r = g_S + row * T;
    int t = threadIdx.x;
    float v[4]; float m = -1e30f;
#pragma unroll
    for (int i = 0; i < 4; i++) { v[i] = r[t + 256*i]; m = fmaxf(m, v[i]); }
#pragma unroll
    for (int o = 16; o; o >>= 1) m = fmaxf(m, __shfl_xor_sync(0xffffffffu, m, o));
    __shared__ float sh[8];
    int w = t >> 5, lane = t & 31;
    if (!lane) sh[w] = m;
    __syncthreads();
    __shared__ float m_s, inv_s;
    if (t == 0) {
        float mm = sh[0];
#pragma unroll
        for (int i = 1; i < 8; i++) mm = fmaxf(mm, sh[i]);
        m_s = mm;
    }
    __syncthreads();
    m = m_s;
    float s = 0.f;
#pragma unroll
    for (int i = 0; i < 4; i++) { v[i] = expf(v[i] - m); s += v[i]; }
#pragma unroll
    for (int o = 16; o; o >>= 1) s += __shfl_xor_sync(0xffffffffu, s, o);
    if (!lane) sh[w] = s;
    __syncthreads();
    if (t == 0) {
        float ss = 0.f;
#pragma unroll
        for (int i = 0; i < 8; i++) ss += sh[i];
        inv_s = 1.f / ss;
    }
    __syncthreads();
    float inv = inv_s;
#pragma unroll
    for (int i = 0; i < 4; i++) r[t + 256*i] = v[i] * inv;
}

// ---------------- AV (fp32 SIMT) ----------------
__global__ __launch_bounds__(256) void gemm_av()
{
    int z = blockIdx.z; int bb = z >> 4; int hh = z & 15;
    const float* A  = g_S + (size_t)z*T*T;
    const float* Bm = g_v + (size_t)bb*T*C + hh*HD;
    float* Cc = g_y + (size_t)bb*T*C + hh*HD;
    int rowBase = blockIdx.y * 128;
    int tid = threadIdx.x;
    int tx = tid & 15, ty = tid >> 4;
    __shared__ float As[8][128];
    __shared__ float Bs[8][128];
    float acc[8][8];
#pragma unroll
    for (int i = 0; i < 8; i++)
#pragma unroll
        for (int j = 0; j < 8; j++) acc[i][j] = 0.f;
    int lr = tid >> 1;
    int lc = (tid & 1) << 2;
    int brow = tid >> 5;
    int bcol = (tid & 31) << 2;
    for (int k0 = 0; k0 < T; k0 += 8) {
        float4 av = ld4(A + (size_t)(rowBase+lr)*T + k0 + lc);
        As[lc+0][lr]=av.x; As[lc+1][lr]=av.y; As[lc+2][lr]=av.z; As[lc+3][lr]=av.w;
        float4 bv = make_float4(0,0,0,0);
        if (bcol < HD) bv = ld4(Bm + (size_t)(k0+brow)*C + bcol);
        Bs[brow][bcol+0]=bv.x; Bs[brow][bcol+1]=bv.y; Bs[brow][bcol+2]=bv.z; Bs[brow][bcol+3]=bv.w;
        __syncthreads();
#pragma unroll
        for (int kk = 0; kk < 8; kk++) {
            float4 a0 = ld4(&As[kk][ty*8]), a1 = ld4(&As[kk][ty*8+4]);
            float4 b0 = ld4(&Bs[kk][tx*8]), b1 = ld4(&Bs[kk][tx*8+4]);
            float ra[8] = {a0.x,a0.y,a0.z,a0.w,a1.x,a1.y,a1.z,a1.w};
            float rb[8] = {b0.x,b0.y,b0.z,b0.w,b1.x,b1.y,b1.z,b1.w};
#pragma unroll
            for (int i = 0; i < 8; i++)
#pragma unroll
                for (int j = 0; j < 8; j++) acc[i][j] = fmaf(ra[i], rb[j], acc[i][j]);
        }
        __syncthreads();
    }
#pragma unroll
    for (int i = 0; i < 8; i++) {
        int r = rowBase + ty*8 + i;
        float* crow = Cc + (size_t)r * C;
#pragma unroll
        for (int j = 0; j < 8; j++) {
            int c = tx*8 + j;
            if (c < HD) crow[c] = acc[i][j];
        }
    }
}

// ---------------- gate / routing (reads EXACT h2) ----------------
__global__ void gate_kernel(const float* __restrict__ gW, const float* __restrict__ gb)
{
    int token = blockIdx.x * 4 + (threadIdx.x >> 5);
    int lane = threadIdx.x & 31;
    const float* hr = g_h2 + (size_t)token * C;
    float logits[E];
#pragma unroll
    for (int e = 0; e < E; e++) {
        const float* wr = gW + (size_t)e * C;
        float s = 0.f;
        for (int j = lane; j < C; j += 32) s += hr[j] * wr[j];
#pragma unroll
        for (int o = 16; o; o >>= 1) s += __shfl_xor_sync(0xffffffffu, s, o);
        logits[e] = s + gb[e];
    }
    if (lane == 0) {
        int i0 = 0; float m0 = logits[0];
#pragma unroll
        for (int e = 1; e < E; e++) if (logits[e] > m0) { m0 = logits[e]; i0 = e; }
        int i1 = -1; float m1 = -1e30f;
#pragma unroll
        for (int e = 0; e < E; e++) if (e != i0 && logits[e] > m1) { m1 = logits[e]; i1 = e; }
        float den = 0.f;
#pragma unroll
        for (int e = 0; e < E; e++) den += expf(logits[e] - m0);
        float s0 = 1.f / den;
        float s1 = expf(m1 - m0) / den;
        g_expidx[token*2+0] = i0; g_gscore[token*2+0] = s0;
        g_expidx[token*2+1] = i1; g_gscore[token*2+1] = s1;
        g_pos[token*2+0] = atomicAdd(&g_cnt[i0], 1);
        g_pos[token*2+1] = atomicAdd(&g_cnt[i1], 1);
    }
}

__global__ void zero_cnt_kernel() { if (threadIdx.x < E) g_cnt[threadIdx.x] = 0; }

__global__ void scan_kernel()
{
    if (threadIdx.x == 0) {
        int acc = 0;
        for (int e = 0; e < E; e++) { g_off[e] = acc; acc += g_cnt[e]; }
    }
}

__global__ void scatter_kernel()
{
    int i = blockIdx.x * 256 + threadIdx.x;
    if (i < NASSIGN) {
        int e = g_expidx[i];
        int slot = g_off[e] + g_pos[i];
        g_list[slot] = i >> 1;
        g_slotscore[slot] = g_gscore[i];
    }
}

// ---------------- host launcher ----------------
extern "C" void kernel_launch(void* const* d_in, const int* in_sizes, int n_in,
                              void* d_out, int out_size)
{
    const float* x     = (const float*)d_in[0];
    const float* ln1g  = (const float*)d_in[1];
    const float* ln1b  = (const float*)d_in[2];
    const float* Wq    = (const float*)d_in[3];
    const float* Wk    = (const float*)d_in[4];
    const float* Wv    = (const float*)d_in[5];
    const float* Wo    = (const float*)d_in[6];
    const float* bo    = (const float*)d_in[7];
    const float* ln2g  = (const float*)d_in[8];
    const float* ln2b  = (const float*)d_in[9];
    const float* gateW = (const float*)d_in[10];
    const float* gateb = (const float*)d_in[11];
    const float* fcW   = (const float*)d_in[12];
    const float* fcb   = (const float*)d_in[13];
    const float* pjW   = (const float*)d_in[14];
    const float* pjb   = (const float*)d_in[15];
    float* outp = (float*)d_out;

    float *p_h, *p_q, *p_k, *p_v, *p_y, *p_x1, *p_h2, *p_h2r, *p_fcw, *p_pjw;
    cudaGetSymbolAddress((void**)&p_h,   g_h);
    cudaGetSymbolAddress((void**)&p_q,   g_q);
    cudaGetSymbolAddress((void**)&p_k,   g_k);
    cudaGetSymbolAddress((void**)&p_v,   g_v);
    cudaGetSymbolAddress((void**)&p_y,   g_y);
    cudaGetSymbolAddress((void**)&p_x1,  g_x1);
    cudaGetSymbolAddress((void**)&p_h2,  g_h2);
    cudaGetSymbolAddress((void**)&p_h2r, g_h2r);
    cudaGetSymbolAddress((void**)&p_fcw, g_fcw);
    cudaGetSymbolAddress((void**)&p_pjw, g_pjw);

    cudaFuncSetAttribute(gemm_fc_tc, cudaFuncAttributeMaxDynamicSharedMemorySize, DYNSMEM);
    cudaFuncSetAttribute(gemm_pj_tc, cudaFuncAttributeMaxDynamicSharedMemorySize, DYNSMEM);

    zero_cnt_kernel<<<1, 32>>>();

    // tf32-round MoE weights (unbiased rna)
    conv_tf32<<<8192, 256>>>(fcW, p_fcw, E*FF*C/4);
    conv_tf32<<<8192, 256>>>(pjW, p_pjw, E*C*FF/4);

    // LN1 (exact fp32 only)
    ln_kernel<<<BT, 256>>>(x, ln1g, ln1b, p_h, nullptr);

    // QKV (fp32 SIMT)
    dim3 gQKV(C/128, BT/128);
    gemm_nt<<<gQKV, 256>>>(p_h, C, Wq, C, p_q, C, C);
    gemm_nt<<<gQKV, 256>>>(p_h, C, Wk, C, p_k, C, C);
    gemm_nt<<<gQKV, 256>>>(p_h, C, Wv, C, p_v, C, C);

    // attention (fp32)
    gemm_scores<<<dim3(T/128, T/128, BH), 256>>>();
    softmax_kernel<<<BH*T, 256>>>();
    gemm_av<<<dim3(1, T/128, BH), 256>>>();

    // Wo + bias + residual (fp32 SIMT), dual write
    gemm_wo<<<dim3(C/128, BT/128), 256>>>(p_y, Wo, bo, x, p_x1, outp);

    // LN2: exact h2 (gate) + tf32-rounded h2r (fc)
    ln_kernel<<<BT, 256>>>(p_x1, ln2g, ln2b, p_h2, p_h2r);

    // gating + routing (exact h2)
    gate_kernel<<<BT/4, 128>>>(gateW, gateb);
    scan_kernel<<<1, 32>>>();
    scatter_kernel<<<NASSIGN/256, 256>>>();

    // expert FFN (tf32 MMA, routed top-2)
    gemm_fc_tc<<<dim3(FF/128, BT/128, E), 256, DYNSMEM>>>(fcb);
    gemm_pj_tc<<<dim3(C/128, BT/128, E), 256, DYNSMEM>>>(pjb, outp);
}

// round 7
// speedup vs baseline: 2.6191x; 1.2571x over previous
#include <cuda_runtime.h>
#include <math.h>
#include <stdint.h>

#define Bb 4
#define T 1024
#define C 1024
#define NH 16
#define HD 64
#define E 8
#define TOPK 2
#define FF 4096
#define BT (Bb*T)
#define BH (Bb*NH)
#define NASSIGN (BT*TOPK)

// MMA smem tile: 128 rows x 32 floats, padded stride 36 floats (144B)
#define TILEB (128*144)        // 18432 bytes
#define DYNSMEM  (4*TILEB)     // MoE: A0,A1,B0,B1
#define DYNSMEM3 (8*TILEB)     // split: Ah0,Ah1,Al0,Al1,Bh0,Bh1,Bl0,Bl1 = 147456

// ---------------- scratch ----------------
__device__ float g_hhi[BT*C];
__device__ float g_hlo[BT*C];
__device__ float g_q  [BT*C];
__device__ float g_k  [BT*C];
__device__ float g_v  [BT*C];
__device__ float g_S  [(size_t)BH*T*T];
__device__ float g_yhi[BT*C];
__device__ float g_ylo[BT*C];
__device__ float g_x1 [BT*C];
__device__ float g_h2 [BT*C];    // exact (gate)
__device__ float g_h2r[BT*C];    // tf32-rounded (fc A)
__device__ float g_h1 [(size_t)NASSIGN*FF];
__device__ float g_wqh[C*C]; __device__ float g_wql[C*C];
__device__ float g_wkh[C*C]; __device__ float g_wkl[C*C];
__device__ float g_wvh[C*C]; __device__ float g_wvl[C*C];
__device__ float g_woh[C*C]; __device__ float g_wol[C*C];
__device__ float g_fcw[(size_t)E*FF*C];
__device__ float g_pjw[(size_t)E*C*FF];
__device__ int   g_cnt[E];
__device__ int   g_off[E];
__device__ int   g_expidx[NASSIGN];
__device__ int   g_pos  [NASSIGN];
__device__ float g_gscore[NASSIGN];
__device__ int   g_list [NASSIGN];
__device__ float g_slotscore[NASSIGN];

__device__ __forceinline__ float4 ld4(const float* p){ return *reinterpret_cast<const float4*>(p); }
__device__ __forceinline__ float tf32r(float x){
    float o; asm("cvt.rna.tf32.f32 %0, %1;" : "=f"(o) : "f"(x)); return o;
}

// ---------------- PTX helpers ----------------
__device__ __forceinline__ uint32_t smem_u32(const void* p){
    uint32_t a; asm("{ .reg .u64 t; cvta.to.shared.u64 t, %1; cvt.u32.u64 %0, t; }" : "=r"(a) : "l"(p)); return a;
}
__device__ __forceinline__ void cpa16(uint32_t saddr, const void* g, uint32_t srcsize){
    asm volatile("cp.async.cg.shared.global [%0], [%1], 16, %2;" :: "r"(saddr), "l"(g), "r"(srcsize) : "memory");
}
#define CPA_COMMIT() asm volatile("cp.async.commit_group;" ::: "memory")
#define CPA_WAIT1()  asm volatile("cp.async.wait_group 1;" ::: "memory")
#define CPA_WAIT0()  asm volatile("cp.async.wait_group 0;" ::: "memory")

__device__ __forceinline__ void ldsm_x4(uint32_t &r0, uint32_t &r1, uint32_t &r2, uint32_t &r3, uint32_t addr){
    asm volatile("ldmatrix.sync.aligned.m8n8.x4.shared.b16 {%0,%1,%2,%3},[%4];"
                 : "=r"(r0),"=r"(r1),"=r"(r2),"=r"(r3) : "r"(addr));
}
__device__ __forceinline__ void mma_tf32(float* c, const uint32_t* a, const uint32_t* b){
    asm volatile("mma.sync.aligned.m16n8k8.row.col.f32.tf32.tf32.f32 "
                 "{%0,%1,%2,%3},{%4,%5,%6,%7},{%8,%9},{%0,%1,%2,%3};"
                 : "+f"(c[0]),"+f"(c[1]),"+f"(c[2]),"+f"(c[3])
                 : "r"(a[0]),"r"(a[1]),"r"(a[2]),"r"(a[3]), "r"(b[0]),"r"(b[1]));
}

// =============== fragment offset helpers (validated round 5/6) ===============
__device__ __forceinline__ void frag_offsets(int tid, uint32_t a_off[4], uint32_t b_off[2]){
    int lane = tid & 31, wid = tid >> 5;
    int warpM = wid >> 2, warpN = wid & 3;
#pragma unroll
    for (int mi = 0; mi < 4; mi++) {
        int row = warpM*64 + mi*16 + (lane & 7) + ((lane >> 3) & 1)*8;
        int col4 = (lane >> 4) * 4;
        a_off[mi] = (uint32_t)row*144 + (uint32_t)col4*4;
    }
#pragma unroll
    for (int p = 0; p < 2; p++) {
        int n = warpN*32 + p*16 + (lane & 7) + ((lane >> 4) * 8);
        int col4 = ((lane >> 3) & 1) * 4;
        b_off[p] = (uint32_t)n*144 + (uint32_t)col4*4;
    }
}

// ---------------- tf32 1x MMA mainloop (MoE) ----------------
__device__ __forceinline__ void gemm_mainloop(
    const float* const* rowA, const float* const* rowB,
    const float* dummy, int nchunk, char* sm,
    float acc[4][4][4], int tid)
{
    uint32_t base = smem_u32(sm);
    uint32_t a_off[4], b_off[2];
    frag_offsets(tid, a_off, b_off);

#define ISSUE(kc) do { \
        int b_ = (kc) & 1; \
        uint32_t sa_ = base + b_*TILEB; \
        uint32_t sb_ = base + 2*TILEB + b_*TILEB; \
        _Pragma("unroll") \
        for (int q = 0; q < 4; q++) { \
            int idx = tid + 256*q; \
            int row = idx >> 3, c16 = idx & 7; \
            uint32_t off = (uint32_t)row*144 + c16*16; \
            const float* pa = rowA[row]; \
            const void* ga = pa ? (const void*)(pa + (kc)*32 + c16*4) : (const void*)dummy; \
            cpa16(sa_ + off, ga, pa ? 16u : 0u); \
            cpa16(sb_ + off, rowB[row] + (kc)*32 + c16*4, 16u); \
        } \
        CPA_COMMIT(); \
    } while (0)

    ISSUE(0);
    for (int kc = 0; kc < nchunk; kc++) {
        if (kc + 1 < nchunk) { ISSUE(kc+1); CPA_WAIT1(); } else { CPA_WAIT0(); }
        __syncthreads();
        int b = kc & 1;
        uint32_t sa = base + b*TILEB;
        uint32_t sb = base + 2*TILEB + b*TILEB;
#pragma unroll
        for (int ks = 0; ks < 4; ks++) {
            uint32_t afr[4][4];
#pragma unroll
            for (int mi = 0; mi < 4; mi++)
                ldsm_x4(afr[mi][0], afr[mi][1], afr[mi][2], afr[mi][3], sa + a_off[mi] + ks*32);
            uint32_t bfr[4][2];
#pragma unroll
            for (int p = 0; p < 2; p++)
                ldsm_x4(bfr[2*p][0], bfr[2*p][1], bfr[2*p+1][0], bfr[2*p+1][1], sb + b_off[p] + ks*32);
#pragma unroll
            for (int mi = 0; mi < 4; mi++)
#pragma unroll
                for (int ni = 0; ni < 4; ni++)
                    mma_tf32(acc[mi][ni], afr[mi], bfr[ni]);
        }
        __syncthreads();
    }
#undef ISSUE
}

// ---------------- 3xTF32 split mainloop: C += (Ah+Al)*(Bh+Bl)^T (drop Al*Bl) ----------------
__device__ __forceinline__ void gemm3_mainloop(
    const float* Ah, const float* Al, const float* Bh, const float* Bl,
    int ld, int nchunk, char* sm, float acc[4][4][4], int tid)
{
    uint32_t base = smem_u32(sm);
    uint32_t a_off[4], b_off[2];
    frag_offsets(tid, a_off, b_off);

#define ISSUE3(kc) do { \
        int b_ = (kc) & 1; \
        uint32_t sah_ = base + b_*TILEB; \
        uint32_t sal_ = base + 2*TILEB + b_*TILEB; \
        uint32_t sbh_ = base + 4*TILEB + b_*TILEB; \
        uint32_t sbl_ = base + 6*TILEB + b_*TILEB; \
        _Pragma("unroll") \
        for (int q = 0; q < 4; q++) { \
            int idx = tid + 256*q; \
            int row = idx >> 3, c16 = idx & 7; \
            uint32_t off = (uint32_t)row*144 + c16*16; \
            size_t go = (size_t)row*ld + (kc)*32 + c16*4; \
            cpa16(sah_ + off, Ah + go, 16u); \
            cpa16(sal_ + off, Al + go, 16u); \
            cpa16(sbh_ + off, Bh + go, 16u); \
            cpa16(sbl_ + off, Bl + go, 16u); \
        } \
        CPA_COMMIT(); \
    } while (0)

    ISSUE3(0);
    for (int kc = 0; kc < nchunk; kc++) {
        if (kc + 1 < nchunk) { ISSUE3(kc+1); CPA_WAIT1(); } else { CPA_WAIT0(); }
        __syncthreads();
        int b = kc & 1;
        uint32_t sah = base + b*TILEB;
        uint32_t sal = base + 2*TILEB + b*TILEB;
        uint32_t sbh = base + 4*TILEB + b*TILEB;
        uint32_t sbl = base + 6*TILEB + b*TILEB;
#pragma unroll
        for (int ks = 0; ks < 4; ks++) {
            uint32_t bh[4][2], bl[4][2];
#pragma unroll
            for (int p = 0; p < 2; p++) {
                ldsm_x4(bh[2*p][0], bh[2*p][1], bh[2*p+1][0], bh[2*p+1][1], sbh + b_off[p] + ks*32);
                ldsm_x4(bl[2*p][0], bl[2*p][1], bl[2*p+1][0], bl[2*p+1][1], sbl + b_off[p] + ks*32);
            }
#pragma unroll
            for (int mi = 0; mi < 4; mi++) {
                uint32_t ah[4], al[4];
                ldsm_x4(ah[0], ah[1], ah[2], ah[3], sah + a_off[mi] + ks*32);
                ldsm_x4(al[0], al[1], al[2], al[3], sal + a_off[mi] + ks*32);
#pragma unroll
                for (int ni = 0; ni < 4; ni++) {
                    mma_tf32(acc[mi][ni], ah, bh[ni]);
                    mma_tf32(acc[mi][ni], ah, bl[ni]);
                    mma_tf32(acc[mi][ni], al, bh[ni]);
                }
            }
        }
        __syncthreads();
    }
#undef ISSUE3
}

// ---------------- QKV via 3xTF32 ----------------
__global__ __launch_bounds__(256) void gemm3_qkv()
{
    extern __shared__ char sm[];
    int tid = threadIdx.x;
    int z = blockIdx.z;
    const float* Bh = (z == 0) ? g_wqh : (z == 1) ? g_wkh : g_wvh;
    const float* Bl = (z == 0) ? g_wql : (z == 1) ? g_wkl : g_wvl;
    float* Cout = (z == 0) ? g_q : (z == 1) ? g_k : g_v;
    int rowBase = blockIdx.y * 128, colBase = blockIdx.x * 128;
    float acc[4][4][4] = {};
    gemm3_mainloop(g_hhi + (size_t)rowBase*C, g_hlo + (size_t)rowBase*C,
                   Bh + (size_t)colBase*C,   Bl + (size_t)colBase*C,
                   C, C/32, sm, acc, tid);
    int lane = tid & 31, wid = tid >> 5, warpM = wid >> 2, warpN = wid & 3;
    int g = lane >> 2, tg = lane & 3;
#pragma unroll
    for (int mi = 0; mi < 4; mi++)
#pragma unroll
        for (int ni = 0; ni < 4; ni++) {
            int r = rowBase + warpM*64 + mi*16 + g;
            int cc = colBase + warpN*32 + ni*8 + tg*2;
            *(float2*)(Cout + (size_t)r*C + cc)     = make_float2(acc[mi][ni][0], acc[mi][ni][1]);
            *(float2*)(Cout + (size_t)(r+8)*C + cc) = make_float2(acc[mi][ni][2], acc[mi][ni][3]);
        }
}

// ---------------- Wo via 3xTF32: out = res + y*Wo^T + bias, dual write ----------------
__global__ __launch_bounds__(256) void gemm3_wo(
    const float* __restrict__ bias, const float* __restrict__ res,
    float* __restrict__ out1, float* __restrict__ out2)
{
    extern __shared__ char sm[];
    int tid = threadIdx.x;
    int rowBase = blockIdx.y * 128, colBase = blockIdx.x * 128;
    float acc[4][4][4] = {};
    gemm3_mainloop(g_yhi + (size_t)rowBase*C, g_ylo + (size_t)rowBase*C,
                   g_woh + (size_t)colBase*C, g_wol + (size_t)colBase*C,
                   C, C/32, sm, acc, tid);
    int lane = tid & 31, wid = tid >> 5, warpM = wid >> 2, warpN = wid & 3;
    int g = lane >> 2, tg = lane & 3;
#pragma unroll
    for (int mi = 0; mi < 4; mi++)
#pragma unroll
        for (int ni = 0; ni < 4; ni++) {
            int r0 = rowBase + warpM*64 + mi*16 + g;
            int cc = colBase + warpN*32 + ni*8 + tg*2;
#pragma unroll
            for (int h = 0; h < 2; h++) {
                int r = r0 + h*8;
                float v0 = acc[mi][ni][2*h+0] + bias[cc]   + res[(size_t)r*C + cc];
                float v1 = acc[mi][ni][2*h+1] + bias[cc+1] + res[(size_t)r*C + cc + 1];
                *(float2*)(out1 + (size_t)r*C + cc) = make_float2(v0, v1);
                *(float2*)(out2 + (size_t)r*C + cc) = make_float2(v0, v1);
            }
        }
}

// ---------------- fc: gathered A, +bias, GELU, tf32-rounded out (tf32 MMA) ----------------
__global__ __launch_bounds__(256) void gemm_fc_tc(const float* __restrict__ fcb)
{
    int e = blockIdx.z;
    int cnt = g_cnt[e], off = g_off[e];
    int rowBase = blockIdx.y * 128;
    if (rowBase >= cnt) return;
    int colBase = blockIdx.x * 128;
    extern __shared__ char sm[];
    __shared__ const float* rowA[128];
    __shared__ const float* rowB[128];
    int tid = threadIdx.x;
    const float* wbase = g_fcw + (size_t)e * FF * C;
    if (tid < 128) {
        int r = rowBase + tid;
        rowA[tid] = (r < cnt) ? g_h2r + (size_t)g_list[off + r] * C : nullptr;
        rowB[tid] = wbase + (size_t)(colBase + tid) * C;
    }
    __syncthreads();
    float acc[4][4][4] = {};
    gemm_mainloop(rowA, rowB, wbase, C/32, sm, acc, tid);
    int lane = tid & 31, wid = tid >> 5, warpM = wid >> 2, warpN = wid & 3;
    int g = lane >> 2, tg = lane & 3;
    const float* fb = fcb + (size_t)e * FF;
#pragma unroll
    for (int mi = 0; mi < 4; mi++)
#pragma unroll
        for (int ni = 0; ni < 4; ni++) {
            int r0 = rowBase + warpM*64 + mi*16 + g;
            int cc = colBase + warpN*32 + ni*8 + tg*2;
#pragma unroll
            for (int h = 0; h < 2; h++) {
                int r = r0 + h*8;
                if (r >= cnt) continue;
                float v0 = acc[mi][ni][2*h+0] + fb[cc];
                float v1 = acc[mi][ni][2*h+1] + fb[cc+1];
                v0 = v0 * 0.5f * (1.f + erff(v0 * 0.70710678118654752f));
                v1 = v1 * 0.5f * (1.f + erff(v1 * 0.70710678118654752f));
                *(float2*)(g_h1 + (size_t)(off + r)*FF + cc) = make_float2(tf32r(v0), tf32r(v1));
            }
        }
}

// ---------------- pj: +bias, gate-scale, atomicAdd (tf32 MMA) ----------------
__global__ __launch_bounds__(256) void gemm_pj_tc(const float* __restrict__ pjb,
                                                  float* __restrict__ outp)
{
    int e = blockIdx.z;
    int cnt = g_cnt[e], off = g_off[e];
    int rowBase = blockIdx.y * 128;
    if (rowBase >= cnt) return;
    int colBase = blockIdx.x * 128;
    extern __shared__ char sm[];
    __shared__ const float* rowA[128];
    __shared__ const float* rowB[128];
    int tid = threadIdx.x;
    const float* wbase = g_pjw + (size_t)e * C * FF;
    if (tid < 128) {
        int r = rowBase + tid;
        rowA[tid] = (r < cnt) ? g_h1 + (size_t)(off + r) * FF : nullptr;
        rowB[tid] = wbase + (size_t)(colBase + tid) * FF;
    }
    __syncthreads();
    float acc[4][4][4] = {};
    gemm_mainloop(rowA, rowB, wbase, FF/32, sm, acc, tid);
    int lane = tid & 31, wid = tid >> 5, warpM = wid >> 2, warpN = wid & 3;
    int g = lane >> 2, tg = lane & 3;
    const float* pb = pjb + (size_t)e * C;
#pragma unroll
    for (int mi = 0; mi < 4; mi++)
#pragma unroll
        for (int ni = 0; ni < 4; ni++) {
            int r0 = rowBase + warpM*64 + mi*16 + g;
            int cc = colBase + warpN*32 + ni*8 + tg*2;
#pragma unroll
            for (int h = 0; h < 2; h++) {
                int r = r0 + h*8;
                if (r >= cnt) continue;
                int tok = g_list[off + r];
                float sc = g_slotscore[off + r];
                float* orow = outp + (size_t)tok * C;
                atomicAdd(&orow[cc],   sc * (acc[mi][ni][2*h+0] + pb[cc]));
                atomicAdd(&orow[cc+1], sc * (acc[mi][ni][2*h+1] + pb[cc+1]));
            }
        }
}

// ---------------- fp32 -> tf32-rounded fp32 (in place target) ----------------
__global__ void conv_tf32(const float* __restrict__ in, float* __restrict__ out, int n4)
{
    int stride = gridDim.x * blockDim.x;
    for (int idx = blockIdx.x * blockDim.x + threadIdx.x; idx < n4; idx += stride) {
        float4 v = ((const float4*)in)[idx];
        v.x = tf32r(v.x); v.y = tf32r(v.y); v.z = tf32r(v.z); v.w = tf32r(v.w);
        ((float4*)out)[idx] = v;
    }
}

// ---------------- fp32 -> (hi, lo) split ----------------
__global__ void conv_split(const float* __restrict__ in, float* __restrict__ hi,
                           float* __restrict__ lo, int n4)
{
    int stride = gridDim.x * blockDim.x;
    for (int idx = blockIdx.x * blockDim.x + threadIdx.x; idx < n4; idx += stride) {
        float4 v = ((const float4*)in)[idx];
        float4 h, l;
        h.x = tf32r(v.x); l.x = tf32r(v.x - h.x);
        h.y = tf32r(v.y); l.y = tf32r(v.y - h.y);
        h.z = tf32r(v.z); l.z = tf32r(v.z - h.z);
        h.w = tf32r(v.w); l.w = tf32r(v.w - h.w);
        ((float4*)hi)[idx] = h;
        ((float4*)lo)[idx] = l;
    }
}

// ---------------- layernorm: optional exact / tf32-rounded / split outputs ----------------
__global__ void ln_kernel(const float* __restrict__ x, const float* __restrict__ g,
                          const float* __restrict__ b, float* __restrict__ outf,
                          float* __restrict__ outr,
                          float* __restrict__ outhi, float* __restrict__ outlo)
{
    int row = blockIdx.x;
    const float* xr = x + (size_t)row * C;
    int t = threadIdx.x;
    float v[4]; float s = 0.f, s2 = 0.f;
#pragma unroll
    for (int i = 0; i < 4; i++) { float val = xr[t + 256*i]; v[i] = val; s += val; s2 += val*val; }
#pragma unroll
    for (int o = 16; o; o >>= 1) { s += __shfl_xor_sync(0xffffffffu, s, o); s2 += __shfl_xor_sync(0xffffffffu, s2, o); }
    __shared__ float sh[8], sh2[8];
    int w = t >> 5, lane = t & 31;
    if (!lane) { sh[w] = s; sh2[w] = s2; }
    __syncthreads();
    __shared__ float mean_s, rstd_s;
    if (t == 0) {
        float S = 0.f, S2 = 0.f;
#pragma unroll
        for (int i = 0; i < 8; i++) { S += sh[i]; S2 += sh2[i]; }
        float mean = S * (1.f/C);
        float var  = S2 * (1.f/C) - mean*mean;
        mean_s = mean; rstd_s = rsqrtf(var + 1e-5f);
    }
    __syncthreads();
    float mean = mean_s, rstd = rstd_s;
#pragma unroll
    for (int i = 0; i < 4; i++) {
        int c = t + 256*i;
        float o = (v[i] - mean) * rstd * g[c] + b[c];
        size_t p = (size_t)row*C + c;
        if (outf) outf[p] = o;
        if (outr) outr[p] = tf32r(o);
        if (outhi) { float hh = tf32r(o); outhi[p] = hh; outlo[p] = tf32r(o - hh); }
    }
}

// ---------------- attention scores (fp32, causal; masked tiles skipped entirely) ----------------
__global__ __launch_bounds__(256) void gemm_scores()
{
    int z = blockIdx.z; int bb = z >> 4; int hh = z & 15;
    int rowBase = blockIdx.y * 128;
    int colBase = blockIdx.x * 128;
    if (colBase >= rowBase + 128) return;   // never read downstream
    const float* A  = g_q + (size_t)bb*T*C + hh*HD;
    const float* Bw = g_k + (size_t)bb*T*C + hh*HD;
    float* Cc = g_S + (size_t)z*T*T;
    int tid = threadIdx.x;
    int tx = tid & 15, ty = tid >> 4;
    __shared__ float As[8][128];
    __shared__ float Bs[8][128];
    float acc[8][8];
#pragma unroll
    for (int i = 0; i < 8; i++)
#pragma unroll
        for (int j = 0; j < 8; j++) acc[i][j] = 0.f;
    int lr = tid >> 1;
    int lc = (tid & 1) << 2;
    for (int k0 = 0; k0 < HD; k0 += 8) {
        float4 av = ld4(A  + (size_t)(rowBase+lr)*C + k0 + lc);
        float4 bv = ld4(Bw + (size_t)(colBase+lr)*C + k0 + lc);
        As[lc+0][lr]=av.x; As[lc+1][lr]=av.y; As[lc+2][lr]=av.z; As[lc+3][lr]=av.w;
        Bs[lc+0][lr]=bv.x; Bs[lc+1][lr]=bv.y; Bs[lc+2][lr]=bv.z; Bs[lc+3][lr]=bv.w;
        __syncthreads();
#pragma unroll
        for (int kk = 0; kk < 8; kk++) {
            float4 a0 = ld4(&As[kk][ty*8]), a1 = ld4(&As[kk][ty*8+4]);
            float4 b0 = ld4(&Bs[kk][tx*8]), b1 = ld4(&Bs[kk][tx*8+4]);
            float ra[8] = {a0.x,a0.y,a0.z,a0.w,a1.x,a1.y,a1.z,a1.w};
            float rb[8] = {b0.x,b0.y,b0.z,b0.w,b1.x,b1.y,b1.z,b1.w};
#pragma unroll
            for (int i = 0; i < 8; i++)
#pragma unroll
                for (int j = 0; j < 8; j++) acc[i][j] = fmaf(ra[i], rb[j], acc[i][j]);
        }
        __syncthreads();
    }
#pragma unroll
    for (int i = 0; i < 8; i++) {
        int r = rowBase + ty*8 + i;
        float* crow = Cc + (size_t)r * T;
#pragma unroll
        for (int j = 0; j < 8; j++) {
            int c = colBase + tx*8 + j;
            crow[c] = (c <= r) ? acc[i][j] * 0.125f : -1e30f;
        }
    }
}

// ---------------- row softmax (only valid 128-blocks) ----------------
__global__ void softmax_kernel()
{
    size_t row = blockIdx.x;
    int r = (int)(row & (T-1));
    int nv = ((r >> 7) + 1) << 7;   // valid length, multiple of 128 (= AV read region)
    float* rp = g_S + row * T;
    int t = threadIdx.x;
    float v[4]; float m = -1e30f;
#pragma unroll
    for (int i = 0; i < 4; i++) {
        int idx = t + 256*i;
        v[i] = (idx < nv) ? rp[idx] : -1e30f;
        m = fmaxf(m, v[i]);
    }
#pragma unroll
    for (int o = 16; o; o >>= 1) m = fmaxf(m, __shfl_xor_sync(0xffffffffu, m, o));
    __shared__ float sh[8];
    int w = t >> 5, lane = t & 31;
    if (!lane) sh[w] = m;
    __syncthreads();
    __shared__ float m_s, inv_s;
    if (t == 0) {
        float mm = sh[0];
#pragma unroll
        for (int i = 1; i < 8; i++) mm = fmaxf(mm, sh[i]);
        m_s = mm;
    }
    __syncthreads();
    m = m_s;
    float s = 0.f;
#pragma unroll
    for (int i = 0; i < 4; i++) { v[i] = expf(v[i] - m); s += v[i]; }
#pragma unroll
    for (int o = 16; o; o >>= 1) s += __shfl_xor_sync(0xffffffffu, s, o);
    if (!lane) sh[w] = s;
    __syncthreads();
    if (t == 0) {
        float ss = 0.f;
#pragma unroll
        for (int i = 0; i < 8; i++) ss += sh[i];
        inv_s = 1.f / ss;
    }
    __syncthreads();
    float inv = inv_s;
#pragma unroll
    for (int i = 0; i < 4; i++) {
        int idx = t + 256*i;
        if (idx < nv) rp[idx] = v[i] * inv;
    }
}

// ---------------- AV (fp32 SIMT, causal k-bound, split y output) ----------------
__global__ __launch_bounds__(256) void gemm_av()
{
    int z = blockIdx.z; int bb = z >> 4; int hh = z & 15;
    const float* A  = g_S + (size_t)z*T*T;
    const float* Bm = g_v + (size_t)bb*T*C + hh*HD;
    size_t ybase = (size_t)bb*T*C + hh*HD;
    int rowBase = blockIdx.y * 128;
    int kmax = rowBase + 128;           // causal: probs zero beyond this
    int tid = threadIdx.x;
    int tx = tid & 15, ty = tid >> 4;
    __shared__ float As[8][128];
    __shared__ float Bs[8][128];
    float acc[8][8];
#pragma unroll
    for (int i = 0; i < 8; i++)
#pragma unroll
        for (int j = 0; j < 8; j++) acc[i][j] = 0.f;
    int lr = tid >> 1;
    int lc = (tid & 1) << 2;
    int brow = tid >> 5;
    int bcol = (tid & 31) << 2;
    for (int k0 = 0; k0 < kmax; k0 += 8) {
        float4 av = ld4(A + (size_t)(rowBase+lr)*T + k0 + lc);
        As[lc+0][lr]=av.x; As[lc+1][lr]=av.y; As[lc+2][lr]=av.z; As[lc+3][lr]=av.w;
        float4 bv = make_float4(0,0,0,0);
        if (bcol < HD) bv = ld4(Bm + (size_t)(k0+brow)*C + bcol);
        Bs[brow][bcol+0]=bv.x; Bs[brow][bcol+1]=bv.y; Bs[brow][bcol+2]=bv.z; Bs[brow][bcol+3]=bv.w;
        __syncthreads();
#pragma unroll
        for (int kk = 0; kk < 8; kk++) {
            float4 a0 = ld4(&As[kk][ty*8]), a1 = ld4(&As[kk][ty*8+4]);
            float4 b0 = ld4(&Bs[kk][tx*8]), b1 = ld4(&Bs[kk][tx*8+4]);
            float ra[8] = {a0.x,a0.y,a0.z,a0.w,a1.x,a1.y,a1.z,a1.w};
            float rb[8] = {b0.x,b0.y,b0.z,b0.w,b1.x,b1.y,b1.z,b1.w};
#pragma unroll
            for (int i = 0; i < 8; i++)
#pragma unroll
                for (int j = 0; j < 8; j++) acc[i][j] = fmaf(ra[i], rb[j], acc[i][j]);
        }
        __syncthreads();
    }
#pragma unroll
    for (int i = 0; i < 8; i++) {
        int r = rowBase + ty*8 + i;
#pragma unroll
        for (int j = 0; j < 8; j++) {
            int c = tx*8 + j;
            if (c < HD) {
                float vv = acc[i][j];
                float hh2 = tf32r(vv);
                size_t p = ybase + (size_t)r*C + c;
                g_yhi[p] = hh2;
                g_ylo[p] = tf32r(vv - hh2);
            }
        }
    }
}

// ---------------- gate / routing (reads EXACT h2) ----------------
__global__ void gate_kernel(const float* __restrict__ gW, const float* __restrict__ gb)
{
    int token = blockIdx.x * 4 + (threadIdx.x >> 5);
    int lane = threadIdx.x & 31;
    const float* hr = g_h2 + (size_t)token * C;
    float logits[E];
#pragma unroll
    for (int e = 0; e < E; e++) {
        const float* wr = gW + (size_t)e * C;
        float s = 0.f;
        for (int j = lane; j < C; j += 32) s += hr[j] * wr[j];
#pragma unroll
        for (int o = 16; o; o >>= 1) s += __shfl_xor_sync(0xffffffffu, s, o);
        logits[e] = s + gb[e];
    }
    if (lane == 0) {
        int i0 = 0; float m0 = logits[0];
#pragma unroll
        for (int e = 1; e < E; e++) if (logits[e] > m0) { m0 = logits[e]; i0 = e; }
        int i1 = -1; float m1 = -1e30f;
#pragma unroll
        for (int e = 0; e < E; e++) if (e != i0 && logits[e] > m1) { m1 = logits[e]; i1 = e; }
        float den = 0.f;
#pragma unroll
        for (int e = 0; e < E; e++) den += expf(logits[e] - m0);
        float s0 = 1.f / den;
        float s1 = expf(m1 - m0) / den;
        g_expidx[token*2+0] = i0; g_gscore[token*2+0] = s0;
        g_expidx[token*2+1] = i1; g_gscore[token*2+1] = s1;
        g_pos[token*2+0] = atomicAdd(&g_cnt[i0], 1);
        g_pos[token*2+1] = atomicAdd(&g_cnt[i1], 1);
    }
}

__global__ void zero_cnt_kernel() { if (threadIdx.x < E) g_cnt[threadIdx.x] = 0; }

__global__ void scan_kernel()
{
    if (threadIdx.x == 0) {
        int acc = 0;
        for (int e = 0; e < E; e++) { g_off[e] = acc; acc += g_cnt[e]; }
    }
}

__global__ void scatter_kernel()
{
    int i = blockIdx.x * 256 + threadIdx.x;
    if (i < NASSIGN) {
        int e = g_expidx[i];
        int slot = g_off[e] + g_pos[i];
        g_list[slot] = i >> 1;
        g_slotscore[slot] = g_gscore[i];
    }
}

// ---------------- host launcher ----------------
extern "C" void kernel_launch(void* const* d_in, const int* in_sizes, int n_in,
                              void* d_out, int out_size)
{
    const float* x     = (const float*)d_in[0];
    const float* ln1g  = (const float*)d_in[1];
    const float* ln1b  = (const float*)d_in[2];
    const float* Wq    = (const float*)d_in[3];
    const float* Wk    = (const float*)d_in[4];
    const float* Wv    = (const float*)d_in[5];
    const float* Wo    = (const float*)d_in[6];
    const float* bo    = (const float*)d_in[7];
    const float* ln2g  = (const float*)d_in[8];
    const float* ln2b  = (const float*)d_in[9];
    const float* gateW = (const float*)d_in[10];
    const float* gateb = (const float*)d_in[11];
    const float* fcW   = (const float*)d_in[12];
    const float* fcb   = (const float*)d_in[13];
    const float* pjW   = (const float*)d_in[14];
    const float* pjb   = (const float*)d_in[15];
    float* outp = (float*)d_out;

    float *p_hhi, *p_hlo, *p_x1, *p_h2, *p_h2r, *p_fcw, *p_pjw;
    float *p_wqh, *p_wql, *p_wkh, *p_wkl, *p_wvh, *p_wvl, *p_woh, *p_wol;
    cudaGetSymbolAddress((void**)&p_hhi, g_hhi);
    cudaGetSymbolAddress((void**)&p_hlo, g_hlo);
    cudaGetSymbolAddress((void**)&p_x1,  g_x1);
    cudaGetSymbolAddress((void**)&p_h2,  g_h2);
    cudaGetSymbolAddress((void**)&p_h2r, g_h2r);
    cudaGetSymbolAddress((void**)&p_fcw, g_fcw);
    cudaGetSymbolAddress((void**)&p_pjw, g_pjw);
    cudaGetSymbolAddress((void**)&p_wqh, g_wqh); cudaGetSymbolAddress((void**)&p_wql, g_wql);
    cudaGetSymbolAddress((void**)&p_wkh, g_wkh); cudaGetSymbolAddress((void**)&p_wkl, g_wkl);
    cudaGetSymbolAddress((void**)&p_wvh, g_wvh); cudaGetSymbolAddress((void**)&p_wvl, g_wvl);
    cudaGetSymbolAddress((void**)&p_woh, g_woh); cudaGetSymbolAddress((void**)&p_wol, g_wol);

    cudaFuncSetAttribute(gemm_fc_tc, cudaFuncAttributeMaxDynamicSharedMemorySize, DYNSMEM);
    cudaFuncSetAttribute(gemm_pj_tc, cudaFuncAttributeMaxDynamicSharedMemorySize, DYNSMEM);
    cudaFuncSetAttribute(gemm3_qkv,  cudaFuncAttributeMaxDynamicSharedMemorySize, DYNSMEM3);
    cudaFuncSetAttribute(gemm3_wo,   cudaFuncAttributeMaxDynamicSharedMemorySize, DYNSMEM3);

    zero_cnt_kernel<<<1, 32>>>();

    // MoE weights: unbiased tf32 rounding
    conv_tf32<<<8192, 256>>>(fcW, p_fcw, E*FF*C/4);
    conv_tf32<<<8192, 256>>>(pjW, p_pjw, E*C*FF/4);

    // Attention weights: hi/lo split
    conv_split<<<2048, 256>>>(Wq, p_wqh, p_wql, C*C/4);
    conv_split<<<2048, 256>>>(Wk, p_wkh, p_wkl, C*C/4);
    conv_split<<<2048, 256>>>(Wv, p_wvh, p_wvl, C*C/4);
    conv_split<<<2048, 256>>>(Wo, p_woh, p_wol, C*C/4);

    // LN1 -> split h
    ln_kernel<<<BT, 256>>>(x, ln1g, ln1b, nullptr, nullptr, p_hhi, p_hlo);

    // QKV (3xTF32 MMA)
    gemm3_qkv<<<dim3(C/128, BT/128, 3), 256, DYNSMEM3>>>();

    // attention (fp32, causal-pruned)
    gemm_scores<<<dim3(T/128, T/128, BH), 256>>>();
    softmax_kernel<<<BH*T, 256>>>();
    gemm_av<<<dim3(1, T/128, BH), 256>>>();

    // Wo + bias + residual (3xTF32 MMA), dual write
    gemm3_wo<<<dim3(C/128, BT/128), 256, DYNSMEM3>>>(bo, x, p_x1, outp);

    // LN2: exact h2 (gate) + tf32-rounded h2r (fc)
    ln_kernel<<<BT, 256>>>(p_x1, ln2g, ln2b, p_h2, p_h2r, nullptr, nullptr);

    // gating + routing (exact h2)
    gate_kernel<<<BT/4, 128>>>(gateW, gateb);
    scan_kernel<<<1, 32>>>();
    scatter_kernel<<<NASSIGN/256, 256>>>();

    // expert FFN (tf32 MMA, routed top-2)
    gemm_fc_tc<<<dim3(FF/128, BT/128, E), 256, DYNSMEM>>>(fcb);
    gemm_pj_tc<<<dim3(C/128, BT/128, E), 256, DYNSMEM>>>(pjb, outp);
}

// round 8
// speedup vs baseline: 2.9650x; 1.1321x over previous
#include <cuda_runtime.h>
#include <math.h>
#include <stdint.h>

#define Bb 4
#define T 1024
#define C 1024
#define NH 16
#define HD 64
#define E 8
#define TOPK 2
#define FF 4096
#define BT (Bb*T)
#define BH (Bb*NH)
#define NASSIGN (BT*TOPK)

// MMA smem tile: 128 rows x 32 floats, padded stride 36 floats (144B)
#define TILEB (128*144)        // 18432 bytes
#define DYNSMEM  (4*TILEB)     // MoE: A0,A1,B0,B1
#define DYNSMEM3 (8*TILEB)     // split: Ah0,Ah1,Al0,Al1,Bh0,Bh1,Bl0,Bl1 = 147456

// ---------------- scratch ----------------
__device__ float g_hhi[BT*C];
__device__ float g_hlo[BT*C];
__device__ float g_qhi[BT*C];
__device__ float g_qlo[BT*C];
__device__ float g_khi[BT*C];
__device__ float g_klo[BT*C];
__device__ float g_v  [BT*C];
__device__ float g_S  [(size_t)BH*T*T];   // logits, then probs-hi
__device__ float g_Slo[(size_t)BH*T*T];   // probs-lo
__device__ float g_vthi[(size_t)BH*128*T]; // v^T, zero-padded rows 64..127
__device__ float g_vtlo[(size_t)BH*128*T];
__device__ float g_yhi[BT*C];
__device__ float g_ylo[BT*C];
__device__ float g_x1 [BT*C];
__device__ float g_h2 [BT*C];    // exact (gate)
__device__ float g_h2r[BT*C];    // tf32-rounded (fc A)
__device__ float g_h1 [(size_t)NASSIGN*FF];
__device__ float g_wqh[C*C]; __device__ float g_wql[C*C];
__device__ float g_wkh[C*C]; __device__ float g_wkl[C*C];
__device__ float g_wvh[C*C]; __device__ float g_wvl[C*C];
__device__ float g_woh[C*C]; __device__ float g_wol[C*C];
__device__ float g_fcw[(size_t)E*FF*C];
__device__ float g_pjw[(size_t)E*C*FF];
__device__ int   g_cnt[E];
__device__ int   g_off[E];
__device__ int   g_expidx[NASSIGN];
__device__ int   g_pos  [NASSIGN];
__device__ float g_gscore[NASSIGN];
__device__ int   g_list [NASSIGN];
__device__ float g_slotscore[NASSIGN];

__device__ __forceinline__ float tf32r(float x){
    float o; asm("cvt.rna.tf32.f32 %0, %1;" : "=f"(o) : "f"(x)); return o;
}

// ---------------- PTX helpers ----------------
__device__ __forceinline__ uint32_t smem_u32(const void* p){
    uint32_t a; asm("{ .reg .u64 t; cvta.to.shared.u64 t, %1; cvt.u32.u64 %0, t; }" : "=r"(a) : "l"(p)); return a;
}
__device__ __forceinline__ void cpa16(uint32_t saddr, const void* g, uint32_t srcsize){
    asm volatile("cp.async.cg.shared.global [%0], [%1], 16, %2;" :: "r"(saddr), "l"(g), "r"(srcsize) : "memory");
}
#define CPA_COMMIT() asm volatile("cp.async.commit_group;" ::: "memory")
#define CPA_WAIT1()  asm volatile("cp.async.wait_group 1;" ::: "memory")
#define CPA_WAIT0()  asm volatile("cp.async.wait_group 0;" ::: "memory")

__device__ __forceinline__ void ldsm_x4(uint32_t &r0, uint32_t &r1, uint32_t &r2, uint32_t &r3, uint32_t addr){
    asm volatile("ldmatrix.sync.aligned.m8n8.x4.shared.b16 {%0,%1,%2,%3},[%4];"
                 : "=r"(r0),"=r"(r1),"=r"(r2),"=r"(r3) : "r"(addr));
}
__device__ __forceinline__ void mma_tf32(float* c, const uint32_t* a, const uint32_t* b){
    asm volatile("mma.sync.aligned.m16n8k8.row.col.f32.tf32.tf32.f32 "
                 "{%0,%1,%2,%3},{%4,%5,%6,%7},{%8,%9},{%0,%1,%2,%3};"
                 : "+f"(c[0]),"+f"(c[1]),"+f"(c[2]),"+f"(c[3])
                 : "r"(a[0]),"r"(a[1]),"r"(a[2]),"r"(a[3]), "r"(b[0]),"r"(b[1]));
}

// =============== fragment offset helpers (validated) ===============
__device__ __forceinline__ void frag_offsets(int tid, uint32_t a_off[4], uint32_t b_off[2]){
    int lane = tid & 31, wid = tid >> 5;
    int warpM = wid >> 2, warpN = wid & 3;
#pragma unroll
    for (int mi = 0; mi < 4; mi++) {
        int row = warpM*64 + mi*16 + (lane & 7) + ((lane >> 3) & 1)*8;
        int col4 = (lane >> 4) * 4;
        a_off[mi] = (uint32_t)row*144 + (uint32_t)col4*4;
    }
#pragma unroll
    for (int p = 0; p < 2; p++) {
        int n = warpN*32 + p*16 + (lane & 7) + ((lane >> 4) * 8);
        int col4 = ((lane >> 3) & 1) * 4;
        b_off[p] = (uint32_t)n*144 + (uint32_t)col4*4;
    }
}

// ---------------- tf32 1x MMA mainloop (MoE) ----------------
__device__ __forceinline__ void gemm_mainloop(
    const float* const* rowA, const float* const* rowB,
    const float* dummy, int nchunk, char* sm,
    float acc[4][4][4], int tid)
{
    uint32_t base = smem_u32(sm);
    uint32_t a_off[4], b_off[2];
    frag_offsets(tid, a_off, b_off);

#define ISSUE(kc) do { \
        int b_ = (kc) & 1; \
        uint32_t sa_ = base + b_*TILEB; \
        uint32_t sb_ = base + 2*TILEB + b_*TILEB; \
        _Pragma("unroll") \
        for (int q = 0; q < 4; q++) { \
            int idx = tid + 256*q; \
            int row = idx >> 3, c16 = idx & 7; \
            uint32_t off = (uint32_t)row*144 + c16*16; \
            const float* pa = rowA[row]; \
            const void* ga = pa ? (const void*)(pa + (kc)*32 + c16*4) : (const void*)dummy; \
            cpa16(sa_ + off, ga, pa ? 16u : 0u); \
            cpa16(sb_ + off, rowB[row] + (kc)*32 + c16*4, 16u); \
        } \
        CPA_COMMIT(); \
    } while (0)

    ISSUE(0);
    for (int kc = 0; kc < nchunk; kc++) {
        if (kc + 1 < nchunk) { ISSUE(kc+1); CPA_WAIT1(); } else { CPA_WAIT0(); }
        __syncthreads();
        int b = kc & 1;
        uint32_t sa = base + b*TILEB;
        uint32_t sb = base + 2*TILEB + b*TILEB;
#pragma unroll
        for (int ks = 0; ks < 4; ks++) {
            uint32_t afr[4][4];
#pragma unroll
            for (int mi = 0; mi < 4; mi++)
                ldsm_x4(afr[mi][0], afr[mi][1], afr[mi][2], afr[mi][3], sa + a_off[mi] + ks*32);
            uint32_t bfr[4][2];
#pragma unroll
            for (int p = 0; p < 2; p++)
                ldsm_x4(bfr[2*p][0], bfr[2*p][1], bfr[2*p+1][0], bfr[2*p+1][1], sb + b_off[p] + ks*32);
#pragma unroll
            for (int mi = 0; mi < 4; mi++)
#pragma unroll
                for (int ni = 0; ni < 4; ni++)
                    mma_tf32(acc[mi][ni], afr[mi], bfr[ni]);
        }
        __syncthreads();
    }
#undef ISSUE
}

// ---------------- 3xTF32 split mainloop: C += (Ah+Al)*(Bh+Bl)^T (drop Al*Bl) ----------------
__device__ __forceinline__ void gemm3_mainloop(
    const float* Ah, const float* Al, const float* Bh, const float* Bl,
    int lda, int ldb, int nchunk, char* sm, float acc[4][4][4], int tid)
{
    uint32_t base = smem_u32(sm);
    uint32_t a_off[4], b_off[2];
    frag_offsets(tid, a_off, b_off);

#define ISSUE3(kc) do { \
        int b_ = (kc) & 1; \
        uint32_t sah_ = base + b_*TILEB; \
        uint32_t sal_ = base + 2*TILEB + b_*TILEB; \
        uint32_t sbh_ = base + 4*TILEB + b_*TILEB; \
        uint32_t sbl_ = base + 6*TILEB + b_*TILEB; \
        _Pragma("unroll") \
        for (int q = 0; q < 4; q++) { \
            int idx = tid + 256*q; \
            int row = idx >> 3, c16 = idx & 7; \
            uint32_t off = (uint32_t)row*144 + c16*16; \
            size_t goa = (size_t)row*lda + (kc)*32 + c16*4; \
            size_t gob = (size_t)row*ldb + (kc)*32 + c16*4; \
            cpa16(sah_ + off, Ah + goa, 16u); \
            cpa16(sal_ + off, Al + goa, 16u); \
            cpa16(sbh_ + off, Bh + gob, 16u); \
            cpa16(sbl_ + off, Bl + gob, 16u); \
        } \
        CPA_COMMIT(); \
    } while (0)

    ISSUE3(0);
    for (int kc = 0; kc < nchunk; kc++) {
        if (kc + 1 < nchunk) { ISSUE3(kc+1); CPA_WAIT1(); } else { CPA_WAIT0(); }
        __syncthreads();
        int b = kc & 1;
        uint32_t sah = base + b*TILEB;
        uint32_t sal = base + 2*TILEB + b*TILEB;
        uint32_t sbh = base + 4*TILEB + b*TILEB;
        uint32_t sbl = base + 6*TILEB + b*TILEB;
#pragma unroll
        for (int ks = 0; ks < 4; ks++) {
            uint32_t bh[4][2], bl[4][2];
#pragma unroll
            for (int p = 0; p < 2; p++) {
                ldsm_x4(bh[2*p][0], bh[2*p][1], bh[2*p+1][0], bh[2*p+1][1], sbh + b_off[p] + ks*32);
                ldsm_x4(bl[2*p][0], bl[2*p][1], bl[2*p+1][0], bl[2*p+1][1], sbl + b_off[p] + ks*32);
            }
#pragma unroll
            for (int mi = 0; mi < 4; mi++) {
                uint32_t ah[4], al[4];
                ldsm_x4(ah[0], ah[1], ah[2], ah[3], sah + a_off[mi] + ks*32);
                ldsm_x4(al[0], al[1], al[2], al[3], sal + a_off[mi] + ks*32);
#pragma unroll
                for (int ni = 0; ni < 4; ni++) {
                    mma_tf32(acc[mi][ni], ah, bh[ni]);
                    mma_tf32(acc[mi][ni], ah, bl[ni]);
                    mma_tf32(acc[mi][ni], al, bh[ni]);
                }
            }
        }
        __syncthreads();
    }
#undef ISSUE3
}

// ---------------- QKV via 3xTF32; q,k written split, v plain ----------------
__global__ __launch_bounds__(256) void gemm3_qkv()
{
    extern __shared__ char sm[];
    int tid = threadIdx.x;
    int z = blockIdx.z;
    const float* Bh = (z == 0) ? g_wqh : (z == 1) ? g_wkh : g_wvh;
    const float* Bl = (z == 0) ? g_wql : (z == 1) ? g_wkl : g_wvl;
    int rowBase = blockIdx.y * 128, colBase = blockIdx.x * 128;
    float acc[4][4][4] = {};
    gemm3_mainloop(g_hhi + (size_t)rowBase*C, g_hlo + (size_t)rowBase*C,
                   Bh + (size_t)colBase*C,   Bl + (size_t)colBase*C,
                   C, C, C/32, sm, acc, tid);
    int lane = tid & 31, wid = tid >> 5, warpM = wid >> 2, warpN = wid & 3;
    int g = lane >> 2, tg = lane & 3;
    float* Hi = (z == 0) ? g_qhi : g_khi;
    float* Lo = (z == 0) ? g_qlo : g_klo;
#pragma unroll
    for (int mi = 0; mi < 4; mi++)
#pragma unroll
        for (int ni = 0; ni < 4; ni++) {
            int r0 = rowBase + warpM*64 + mi*16 + g;
            int cc = colBase + warpN*32 + ni*8 + tg*2;
#pragma unroll
            for (int h = 0; h < 2; h++) {
                int r = r0 + h*8;
                float v0 = acc[mi][ni][2*h+0];
                float v1 = acc[mi][ni][2*h+1];
                size_t p = (size_t)r*C + cc;
                if (z < 2) {
                    float h0 = tf32r(v0), h1 = tf32r(v1);
                    *(float2*)(Hi + p) = make_float2(h0, h1);
                    *(float2*)(Lo + p) = make_float2(tf32r(v0 - h0), tf32r(v1 - h1));
                } else {
                    *(float2*)(g_v + p) = make_float2(v0, v1);
                }
            }
        }
}

// ---------------- scores via 3xTF32 (K=64, causal tile skip) ----------------
__global__ __launch_bounds__(256) void gemm3_scores()
{
    int z = blockIdx.z; int bb = z >> 4; int hh = z & 15;
    int rowBase = blockIdx.y * 128;
    int colBase = blockIdx.x * 128;
    if (colBase >= rowBase + 128) return;
    extern __shared__ char sm[];
    int tid = threadIdx.x;
    size_t aoff = ((size_t)bb*T + rowBase)*C + hh*HD;
    size_t boff = ((size_t)bb*T + colBase)*C + hh*HD;
    float acc[4][4][4] = {};
    gemm3_mainloop(g_qhi + aoff, g_qlo + aoff, g_khi + boff, g_klo + boff,
                   C, C, HD/32, sm, acc, tid);
    float* Cc = g_S + (size_t)z*T*T;
    int lane = tid & 31, wid = tid >> 5, warpM = wid >> 2, warpN = wid & 3;
    int g = lane >> 2, tg = lane & 3;
#pragma unroll
    for (int mi = 0; mi < 4; mi++)
#pragma unroll
        for (int ni = 0; ni < 4; ni++) {
            int r0 = rowBase + warpM*64 + mi*16 + g;
            int cc = colBase + warpN*32 + ni*8 + tg*2;
#pragma unroll
            for (int h = 0; h < 2; h++) {
                int r = r0 + h*8;
                float* crow = Cc + (size_t)r*T;
                crow[cc]   = (cc   <= r) ? acc[mi][ni][2*h+0]*0.125f : -1e30f;
                crow[cc+1] = (cc+1 <= r) ? acc[mi][ni][2*h+1]*0.125f : -1e30f;
            }
        }
}

// ---------------- row softmax (valid 128-blocks only), split output ----------------
__global__ void softmax_kernel()
{
    size_t row = blockIdx.x;
    int r = (int)(row & (T-1));
    int nv = ((r >> 7) + 1) << 7;
    float* rp  = g_S   + row * T;
    float* rlo = g_Slo + row * T;
    int t = threadIdx.x;
    float v[4]; float m = -1e30f;
#pragma unroll
    for (int i = 0; i < 4; i++) {
        int idx = t + 256*i;
        v[i] = (idx < nv) ? rp[idx] : -1e30f;
        m = fmaxf(m, v[i]);
    }
#pragma unroll
    for (int o = 16; o; o >>= 1) m = fmaxf(m, __shfl_xor_sync(0xffffffffu, m, o));
    __shared__ float sh[8];
    int w = t >> 5, lane = t & 31;
    if (!lane) sh[w] = m;
    __syncthreads();
    __shared__ float m_s, inv_s;
    if (t == 0) {
        float mm = sh[0];
#pragma unroll
        for (int i = 1; i < 8; i++) mm = fmaxf(mm, sh[i]);
        m_s = mm;
    }
    __syncthreads();
    m = m_s;
    float s = 0.f;
#pragma unroll
    for (int i = 0; i < 4; i++) { v[i] = expf(v[i] - m); s += v[i]; }
#pragma unroll
    for (int o = 16; o; o >>= 1) s += __shfl_xor_sync(0xffffffffu, s, o);
    if (!lane) sh[w] = s;
    __syncthreads();
    if (t == 0) {
        float ss = 0.f;
#pragma unroll
        for (int i = 0; i < 8; i++) ss += sh[i];
        inv_s = 1.f / ss;
    }
    __syncthreads();
    float inv = inv_s;
#pragma unroll
    for (int i = 0; i < 4; i++) {
        int idx = t + 256*i;
        if (idx < nv) {
            float p = v[i] * inv;
            float hi = tf32r(p);
            rp[idx]  = hi;
            rlo[idx] = tf32r(p - hi);
        }
    }
}

// ---------------- v transpose + split: vT[bh][c(0..127, pad>=64)][k] ----------------
__global__ void transp_split()
{
    __shared__ float tile[32][33];
    int z  = blockIdx.z;                 // head (bh)
    int bb = z >> 4, hh = z & 15;
    int c0 = blockIdx.y * 32;            // 0..96
    int k0 = blockIdx.x * 32;
    int tx = threadIdx.x, ty = threadIdx.y;  // 32 x 8
#pragma unroll
    for (int i = 0; i < 4; i++) {
        int kk = k0 + ty + i*8;
        int cc = c0 + tx;
        float val = (cc < HD) ? g_v[((size_t)bb*T + kk)*C + hh*HD + cc] : 0.f;
        tile[ty + i*8][tx] = val;
    }
    __syncthreads();
#pragma unroll
    for (int i = 0; i < 4; i++) {
        int cc = c0 + ty + i*8;
        int kk = k0 + tx;
        float val = tile[tx][ty + i*8];
        float hi = tf32r(val);
        size_t p = ((size_t)z*128 + cc)*T + kk;
        g_vthi[p] = hi;
        g_vtlo[p] = tf32r(val - hi);
    }
}

// ---------------- AV via 3xTF32 (causal k-bound; N padded to 128, write c<64) ----------------
__global__ __launch_bounds__(256) void gemm3_av()
{
    int z = blockIdx.z; int bb = z >> 4; int hh = z & 15;
    int rowBase = blockIdx.y * 128;
    int nchunk = (rowBase + 128) / 32;
    extern __shared__ char sm[];
    int tid = threadIdx.x;
    size_t aoff = (size_t)z*T*T + (size_t)rowBase*T;
    size_t boff = (size_t)z*128*T;
    float acc[4][4][4] = {};
    gemm3_mainloop(g_S + aoff, g_Slo + aoff, g_vthi + boff, g_vtlo + boff,
                   T, T, nchunk, sm, acc, tid);
    size_t ybase = (size_t)bb*T*C + hh*HD;
    int lane = tid & 31, wid = tid >> 5, warpM = wid >> 2, warpN = wid & 3;
    int g = lane >> 2, tg = lane & 3;
    if (warpN >= 2) return;   // cols 64..127 are zero padding
#pragma unroll
    for (int mi = 0; mi < 4; mi++)
#pragma unroll
        for (int ni = 0; ni < 4; ni++) {
            int r0 = rowBase + warpM*64 + mi*16 + g;
            int cc = warpN*32 + ni*8 + tg*2;
#pragma unroll
            for (int h = 0; h < 2; h++) {
                int r = r0 + h*8;
                float v0 = acc[mi][ni][2*h+0];
                float v1 = acc[mi][ni][2*h+1];
                float h0 = tf32r(v0), h1 = tf32r(v1);
                size_t p = ybase + (size_t)r*C + cc;
                *(float2*)(g_yhi + p) = make_float2(h0, h1);
                *(float2*)(g_ylo + p) = make_float2(tf32r(v0 - h0), tf32r(v1 - h1));
            }
        }
}

// ---------------- Wo via 3xTF32: out = res + y*Wo^T + bias, dual write ----------------
__global__ __launch_bounds__(256) void gemm3_wo(
    const float* __restrict__ bias, const float* __restrict__ res,
    float* __restrict__ out1, float* __restrict__ out2)
{
    extern __shared__ char sm[];
    int tid = threadIdx.x;
    int rowBase = blockIdx.y * 128, colBase = blockIdx.x * 128;
    float acc[4][4][4] = {};
    gemm3_mainloop(g_yhi + (size_t)rowBase*C, g_ylo + (size_t)rowBase*C,
                   g_woh + (size_t)colBase*C, g_wol + (size_t)colBase*C,
                   C, C, C/32, sm, acc, tid);
    int lane = tid & 31, wid = tid >> 5, warpM = wid >> 2, warpN = wid & 3;
    int g = lane >> 2, tg = lane & 3;
#pragma unroll
    for (int mi = 0; mi < 4; mi++)
#pragma unroll
        for (int ni = 0; ni < 4; ni++) {
            int r0 = rowBase + warpM*64 + mi*16 + g;
            int cc = colBase + warpN*32 + ni*8 + tg*2;
#pragma unroll
            for (int h = 0; h < 2; h++) {
                int r = r0 + h*8;
                float v0 = acc[mi][ni][2*h+0] + bias[cc]   + res[(size_t)r*C + cc];
                float v1 = acc[mi][ni][2*h+1] + bias[cc+1] + res[(size_t)r*C + cc + 1];
                *(float2*)(out1 + (size_t)r*C + cc) = make_float2(v0, v1);
                *(float2*)(out2 + (size_t)r*C + cc) = make_float2(v0, v1);
            }
        }
}

// ---------------- fc: gathered A, +bias, GELU, tf32-rounded out (tf32 MMA) ----------------
__global__ __launch_bounds__(256) void gemm_fc_tc(const float* __restrict__ fcb)
{
    int e = blockIdx.z;
    int cnt = g_cnt[e], off = g_off[e];
    int rowBase = blockIdx.y * 128;
    if (rowBase >= cnt) return;
    int colBase = blockIdx.x * 128;
    extern __shared__ char sm[];
    __shared__ const float* rowA[128];
    __shared__ const float* rowB[128];
    int tid = threadIdx.x;
    const float* wbase = g_fcw + (size_t)e * FF * C;
    if (tid < 128) {
        int r = rowBase + tid;
        rowA[tid] = (r < cnt) ? g_h2r + (size_t)g_list[off + r] * C : nullptr;
        rowB[tid] = wbase + (size_t)(colBase + tid) * C;
    }
    __syncthreads();
    float acc[4][4][4] = {};
    gemm_mainloop(rowA, rowB, wbase, C/32, sm, acc, tid);
    int lane = tid & 31, wid = tid >> 5, warpM = wid >> 2, warpN = wid & 3;
    int g = lane >> 2, tg = lane & 3;
    const float* fb = fcb + (size_t)e * FF;
#pragma unroll
    for (int mi = 0; mi < 4; mi++)
#pragma unroll
        for (int ni = 0; ni < 4; ni++) {
            int r0 = rowBase + warpM*64 + mi*16 + g;
            int cc = colBase + warpN*32 + ni*8 + tg*2;
#pragma unroll
            for (int h = 0; h < 2; h++) {
                int r = r0 + h*8;
                if (r >= cnt) continue;
                float v0 = acc[mi][ni][2*h+0] + fb[cc];
                float v1 = acc[mi][ni][2*h+1] + fb[cc+1];
                v0 = v0 * 0.5f * (1.f + erff(v0 * 0.70710678118654752f));
                v1 = v1 * 0.5f * (1.f + erff(v1 * 0.70710678118654752f));
                *(float2*)(g_h1 + (size_t)(off + r)*FF + cc) = make_float2(tf32r(v0), tf32r(v1));
            }
        }
}

// ---------------- pj: +bias, gate-scale, atomicAdd (tf32 MMA) ----------------
__global__ __launch_bounds__(256) void gemm_pj_tc(const float* __restrict__ pjb,
                                                  float* __restrict__ outp)
{
    int e = blockIdx.z;
    int cnt = g_cnt[e], off = g_off[e];
    int rowBase = blockIdx.y * 128;
    if (rowBase >= cnt) return;
    int colBase = blockIdx.x * 128;
    extern __shared__ char sm[];
    __shared__ const float* rowA[128];
    __shared__ const float* rowB[128];
    int tid = threadIdx.x;
    const float* wbase = g_pjw + (size_t)e * C * FF;
    if (tid < 128) {
        int r = rowBase + tid;
        rowA[tid] = (r < cnt) ? g_h1 + (size_t)(off + r) * FF : nullptr;
        rowB[tid] = wbase + (size_t)(colBase + tid) * FF;
    }
    __syncthreads();
    float acc[4][4][4] = {};
    gemm_mainloop(rowA, rowB, wbase, FF/32, sm, acc, tid);
    int lane = tid & 31, wid = tid >> 5, warpM = wid >> 2, warpN = wid & 3;
    int g = lane >> 2, tg = lane & 3;
    const float* pb = pjb + (size_t)e * C;
#pragma unroll
    for (int mi = 0; mi < 4; mi++)
#pragma unroll
        for (int ni = 0; ni < 4; ni++) {
            int r0 = rowBase + warpM*64 + mi*16 + g;
            int cc = colBase + warpN*32 + ni*8 + tg*2;
#pragma unroll
            for (int h = 0; h < 2; h++) {
                int r = r0 + h*8;
                if (r >= cnt) continue;
                int tok = g_list[off + r];
                float sc = g_slotscore[off + r];
                float* orow = outp + (size_t)tok * C;
                atomicAdd(&orow[cc],   sc * (acc[mi][ni][2*h+0] + pb[cc]));
                atomicAdd(&orow[cc+1], sc * (acc[mi][ni][2*h+1] + pb[cc+1]));
            }
        }
}

// ---------------- fp32 -> tf32-rounded fp32 ----------------
__global__ void conv_tf32(const float* __restrict__ in, float* __restrict__ out, int n4)
{
    int stride = gridDim.x * blockDim.x;
    for (int idx = blockIdx.x * blockDim.x + threadIdx.x; idx < n4; idx += stride) {
        float4 v = ((const float4*)in)[idx];
        v.x = tf32r(v.x); v.y = tf32r(v.y); v.z = tf32r(v.z); v.w = tf32r(v.w);
        ((float4*)out)[idx] = v;
    }
}

// ---------------- fp32 -> (hi, lo) split ----------------
__global__ void conv_split(const float* __restrict__ in, float* __restrict__ hi,
                           float* __restrict__ lo, int n4)
{
    int stride = gridDim.x * blockDim.x;
    for (int idx = blockIdx.x * blockDim.x + threadIdx.x; idx < n4; idx += stride) {
        float4 v = ((const float4*)in)[idx];
        float4 h, l;
        h.x = tf32r(v.x); l.x = tf32r(v.x - h.x);
        h.y = tf32r(v.y); l.y = tf32r(v.y - h.y);
        h.z = tf32r(v.z); l.z = tf32r(v.z - h.z);
        h.w = tf32r(v.w); l.w = tf32r(v.w - h.w);
        ((float4*)hi)[idx] = h;
        ((float4*)lo)[idx] = l;
    }
}

// ---------------- layernorm: optional exact / tf32-rounded / split outputs ----------------
__global__ void ln_kernel(const float* __restrict__ x, const float* __restrict__ g,
                          const float* __restrict__ b, float* __restrict__ outf,
                          float* __restrict__ outr,
                          float* __restrict__ outhi, float* __restrict__ outlo)
{
    int row = blockIdx.x;
    const float* xr = x + (size_t)row * C;
    int t = threadIdx.x;
    float v[4]; float s = 0.f, s2 = 0.f;
#pragma unroll
    for (int i = 0; i < 4; i++) { float val = xr[t + 256*i]; v[i] = val; s += val; s2 += val*val; }
#pragma unroll
    for (int o = 16; o; o >>= 1) { s += __shfl_xor_sync(0xffffffffu, s, o); s2 += __shfl_xor_sync(0xffffffffu, s2, o); }
    __shared__ float sh[8], sh2[8];
    int w = t >> 5, lane = t & 31;
    if (!lane) { sh[w] = s; sh2[w] = s2; }
    __syncthreads();
    __shared__ float mean_s, rstd_s;
    if (t == 0) {
        float S = 0.f, S2 = 0.f;
#pragma unroll
        for (int i = 0; i < 8; i++) { S += sh[i]; S2 += sh2[i]; }
        float mean = S * (1.f/C);
        float var  = S2 * (1.f/C) - mean*mean;
        mean_s = mean; rstd_s = rsqrtf(var + 1e-5f);
    }
    __syncthreads();
    float mean = mean_s, rstd = rstd_s;
#pragma unroll
    for (int i = 0; i < 4; i++) {
        int c = t + 256*i;
        float o = (v[i] - mean) * rstd * g[c] + b[c];
        size_t p = (size_t)row*C + c;
        if (outf) outf[p] = o;
        if (outr) outr[p] = tf32r(o);
        if (outhi) { float hh = tf32r(o); outhi[p] = hh; outlo[p] = tf32r(o - hh); }
    }
}

// ---------------- gate / routing (reads EXACT h2) ----------------
__global__ void gate_kernel(const float* __restrict__ gW, const float* __restrict__ gb)
{
    int token = blockIdx.x * 4 + (threadIdx.x >> 5);
    int lane = threadIdx.x & 31;
    const float* hr = g_h2 + (size_t)token * C;
    float logits[E];
#pragma unroll
    for (int e = 0; e < E; e++) {
        const float* wr = gW + (size_t)e * C;
        float s = 0.f;
        for (int j = lane; j < C; j += 32) s += hr[j] * wr[j];
#pragma unroll
        for (int o = 16; o; o >>= 1) s += __shfl_xor_sync(0xffffffffu, s, o);
        logits[e] = s + gb[e];
    }
    if (lane == 0) {
        int i0 = 0; float m0 = logits[0];
#pragma unroll
        for (int e = 1; e < E; e++) if (logits[e] > m0) { m0 = logits[e]; i0 = e; }
        int i1 = -1; float m1 = -1e30f;
#pragma unroll
        for (int e = 0; e < E; e++) if (e != i0 && logits[e] > m1) { m1 = logits[e]; i1 = e; }
        float den = 0.f;
#pragma unroll
        for (int e = 0; e < E; e++) den += expf(logits[e] - m0);
        float s0 = 1.f / den;
        float s1 = expf(m1 - m0) / den;
        g_expidx[token*2+0] = i0; g_gscore[token*2+0] = s0;
        g_expidx[token*2+1] = i1; g_gscore[token*2+1] = s1;
        g_pos[token*2+0] = atomicAdd(&g_cnt[i0], 1);
        g_pos[token*2+1] = atomicAdd(&g_cnt[i1], 1);
    }
}

__global__ void zero_cnt_kernel() { if (threadIdx.x < E) g_cnt[threadIdx.x] = 0; }

__global__ void scan_kernel()
{
    if (threadIdx.x == 0) {
        int acc = 0;
        for (int e = 0; e < E; e++) { g_off[e] = acc; acc += g_cnt[e]; }
    }
}

__global__ void scatter_kernel()
{
    int i = blockIdx.x * 256 + threadIdx.x;
    if (i < NASSIGN) {
        int e = g_expidx[i];
        int slot = g_off[e] + g_pos[i];
        g_list[slot] = i >> 1;
        g_slotscore[slot] = g_gscore[i];
    }
}

// ---------------- host launcher ----------------
extern "C" void kernel_launch(void* const* d_in, const int* in_sizes, int n_in,
                              void* d_out, int out_size)
{
    const float* x     = (const float*)d_in[0];
    const float* ln1g  = (const float*)d_in[1];
    const float* ln1b  = (const float*)d_in[2];
    const float* Wq    = (const float*)d_in[3];
    const float* Wk    = (const float*)d_in[4];
    const float* Wv    = (const float*)d_in[5];
    const float* Wo    = (const float*)d_in[6];
    const float* bo    = (const float*)d_in[7];
    const float* ln2g  = (const float*)d_in[8];
    const float* ln2b  = (const float*)d_in[9];
    const float* gateW = (const float*)d_in[10];
    const float* gateb = (const float*)d_in[11];
    const float* fcW   = (const float*)d_in[12];
    const float* fcb   = (const float*)d_in[13];
    const float* pjW   = (const float*)d_in[14];
    const float* pjb   = (const float*)d_in[15];
    float* outp = (float*)d_out;

    float *p_hhi, *p_hlo, *p_x1, *p_h2, *p_h2r, *p_fcw, *p_pjw;
    float *p_wqh, *p_wql, *p_wkh, *p_wkl, *p_wvh, *p_wvl, *p_woh, *p_wol;
    cudaGetSymbolAddress((void**)&p_hhi, g_hhi);
    cudaGetSymbolAddress((void**)&p_hlo, g_hlo);
    cudaGetSymbolAddress((void**)&p_x1,  g_x1);
    cudaGetSymbolAddress((void**)&p_h2,  g_h2);
    cudaGetSymbolAddress((void**)&p_h2r, g_h2r);
    cudaGetSymbolAddress((void**)&p_fcw, g_fcw);
    cudaGetSymbolAddress((void**)&p_pjw, g_pjw);
    cudaGetSymbolAddress((void**)&p_wqh, g_wqh); cudaGetSymbolAddress((void**)&p_wql, g_wql);
    cudaGetSymbolAddress((void**)&p_wkh, g_wkh); cudaGetSymbolAddress((void**)&p_wkl, g_wkl);
    cudaGetSymbolAddress((void**)&p_wvh, g_wvh); cudaGetSymbolAddress((void**)&p_wvl, g_wvl);
    cudaGetSymbolAddress((void**)&p_woh, g_woh); cudaGetSymbolAddress((void**)&p_wol, g_wol);

    cudaFuncSetAttribute(gemm_fc_tc,   cudaFuncAttributeMaxDynamicSharedMemorySize, DYNSMEM);
    cudaFuncSetAttribute(gemm_pj_tc,   cudaFuncAttributeMaxDynamicSharedMemorySize, DYNSMEM);
    cudaFuncSetAttribute(gemm3_qkv,    cudaFuncAttributeMaxDynamicSharedMemorySize, DYNSMEM3);
    cudaFuncSetAttribute(gemm3_wo,     cudaFuncAttributeMaxDynamicSharedMemorySize, DYNSMEM3);
    cudaFuncSetAttribute(gemm3_scores, cudaFuncAttributeMaxDynamicSharedMemorySize, DYNSMEM3);
    cudaFuncSetAttribute(gemm3_av,     cudaFuncAttributeMaxDynamicSharedMemorySize, DYNSMEM3);

    zero_cnt_kernel<<<1, 32>>>();

    // MoE weights: unbiased tf32 rounding
    conv_tf32<<<8192, 256>>>(fcW, p_fcw, E*FF*C/4);
    conv_tf32<<<8192, 256>>>(pjW, p_pjw, E*C*FF/4);

    // Attention weights: hi/lo split
    conv_split<<<2048, 256>>>(Wq, p_wqh, p_wql, C*C/4);
    conv_split<<<2048, 256>>>(Wk, p_wkh, p_wkl, C*C/4);
    conv_split<<<2048, 256>>>(Wv, p_wvh, p_wvl, C*C/4);
    conv_split<<<2048, 256>>>(Wo, p_woh, p_wol, C*C/4);

    // LN1 -> split h
    ln_kernel<<<BT, 256>>>(x, ln1g, ln1b, nullptr, nullptr, p_hhi, p_hlo);

    // QKV (3xTF32 MMA): q,k split; v plain
    gemm3_qkv<<<dim3(C/128, BT/128, 3), 256, DYNSMEM3>>>();

    // v transpose + split (padded to 128 rows)
    transp_split<<<dim3(T/32, 4, BH), dim3(32, 8)>>>();

    // attention (3xTF32 MMA, causal-pruned)
    gemm3_scores<<<dim3(T/128, T/128, BH), 256, DYNSMEM3>>>();
    softmax_kernel<<<BH*T, 256>>>();
    gemm3_av<<<dim3(1, T/128, BH), 256, DYNSMEM3>>>();

    // Wo + bias + residual (3xTF32 MMA), dual write
    gemm3_wo<<<dim3(C/128, BT/128), 256, DYNSMEM3>>>(bo, x, p_x1, outp);

    // LN2: exact h2 (gate) + tf32-rounded h2r (fc)
    ln_kernel<<<BT, 256>>>(p_x1, ln2g, ln2b, p_h2, p_h2r, nullptr, nullptr);

    // gating + routing (exact h2)
    gate_kernel<<<BT/4, 128>>>(gateW, gateb);
    scan_kernel<<<1, 32>>>();
    scatter_kernel<<<NASSIGN/256, 256>>>();

    // expert FFN (tf32 MMA, routed top-2)
    gemm_fc_tc<<<dim3(FF/128, BT/128, E), 256, DYNSMEM>>>(fcb);
    gemm_pj_tc<<<dim3(C/128, BT/128, E), 256, DYNSMEM>>>(pjb, outp);
}